// round 13
// baseline (speedup 1.0000x reference)
#include <cuda_runtime.h>
#include <math.h>

#define B_   4
#define C_   256
#define H_   32
#define W_   32
#define N_   1024
#define NH_  8
#define HC_  32
#define NG_  4
#define GC_  64
#define BG_  16
#define SCALE_ 0.17677669529663687f   /* 32^-0.5 */
#define EPS_  1e-5f

// ---- scratch (device globals; no allocations allowed) ----
__device__ float g_q  [B_*C_*N_];
__device__ float g_pos[BG_*N_*2];
__device__ float g_xs [B_*C_*N_];
__device__ float g_k  [B_*C_*N_];
__device__ float g_v  [B_*C_*N_];
__device__ float g_o  [B_*C_*N_];

// ---- tf32 mma helpers (3xTF32 error-compensated path) ----
__device__ __forceinline__ unsigned cvt_tf32(float x) {
    unsigned r; asm("cvt.rna.tf32.f32 %0, %1;" : "=r"(r) : "f"(x)); return r;
}
__device__ __forceinline__ void split_tf32(float x, unsigned& hi, unsigned& lo) {
    hi = cvt_tf32(x);
    lo = cvt_tf32(x - __uint_as_float(hi));
}
__device__ __forceinline__ void mma_tf32(float* d, const unsigned* a, const unsigned* b) {
    asm("mma.sync.aligned.m16n8k8.row.col.f32.tf32.tf32.f32 "
        "{%0,%1,%2,%3}, {%4,%5,%6,%7}, {%8,%9}, {%0,%1,%2,%3};"
        : "+f"(d[0]), "+f"(d[1]), "+f"(d[2]), "+f"(d[3])
        : "r"(a[0]), "r"(a[1]), "r"(a[2]), "r"(a[3]), "r"(b[0]), "r"(b[1]));
}

// ============================================================
// Projection GEMM via 3xTF32 tensor mma (unchanged from R12).
// ============================================================
__device__ __forceinline__ void gemm_tile_tf32(
        const float* __restrict__ Wt, const float* __restrict__ bias,
        const float* __restrict__ Xb, float* __restrict__ Yb,
        int p0, int o0, float (*Ws)[72], float (*Xs)[72]) {
    int tid = threadIdx.x;
    int lane = tid & 31, wid = tid >> 5;
    int gid = lane >> 2, tig = lane & 3;
    int wm0 = (wid >> 1) << 5;
    int wn0 = (wid & 1) << 5;

    float acc[2][4][4] = {};

    for (int kt = 0; kt < C_; kt += 16) {
        {
            int o = tid >> 1, kq = (tid & 1) << 3;
            const float* wp = &Wt[(size_t)(o0 + o) * C_ + kt + kq];
            float4 wa = *(const float4*)wp;
            float4 wb = *(const float4*)(wp + 4);
            Ws[kq + 0][o] = wa.x; Ws[kq + 1][o] = wa.y;
            Ws[kq + 2][o] = wa.z; Ws[kq + 3][o] = wa.w;
            Ws[kq + 4][o] = wb.x; Ws[kq + 5][o] = wb.y;
            Ws[kq + 6][o] = wb.z; Ws[kq + 7][o] = wb.w;
        }
#pragma unroll
        for (int it = 0; it < 2; it++) {
            int i4 = tid + (it << 7);
            int k = i4 >> 4, p = (i4 & 15) << 2;
            *(float4*)&Xs[k][p] = *(const float4*)&Xb[(size_t)(kt + k) * N_ + p0 + p];
        }
        __syncthreads();

#pragma unroll
        for (int ks = 0; ks < 16; ks += 8) {
            unsigned ah[2][4], al[2][4], bh[4][2], bl[4][2];
#pragma unroll
            for (int mi = 0; mi < 2; mi++) {
                int r = wm0 + (mi << 4) + gid;
                split_tf32(Ws[ks + tig][r],       ah[mi][0], al[mi][0]);
                split_tf32(Ws[ks + tig][r + 8],   ah[mi][1], al[mi][1]);
                split_tf32(Ws[ks + tig + 4][r],   ah[mi][2], al[mi][2]);
                split_tf32(Ws[ks + tig + 4][r + 8], ah[mi][3], al[mi][3]);
            }
#pragma unroll
            for (int ni = 0; ni < 4; ni++) {
                int cc = wn0 + (ni << 3) + gid;
                split_tf32(Xs[ks + tig][cc],     bh[ni][0], bl[ni][0]);
                split_tf32(Xs[ks + tig + 4][cc], bh[ni][1], bl[ni][1]);
            }
#pragma unroll
            for (int mi = 0; mi < 2; mi++)
#pragma unroll
                for (int ni = 0; ni < 4; ni++) {
                    mma_tf32(acc[mi][ni], ah[mi], bh[ni]);
                    mma_tf32(acc[mi][ni], ah[mi], bl[ni]);
                    mma_tf32(acc[mi][ni], al[mi], bh[ni]);
                }
        }
        __syncthreads();
    }

#pragma unroll
    for (int mi = 0; mi < 2; mi++) {
        int r = wm0 + (mi << 4) + gid;
        float bs0 = bias[o0 + r], bs1 = bias[o0 + r + 8];
#pragma unroll
        for (int ni = 0; ni < 4; ni++) {
            int cb = p0 + wn0 + (ni << 3) + (tig << 1);
            float* y0 = &Yb[(size_t)(o0 + r) * N_ + cb];
            float* y1 = &Yb[(size_t)(o0 + r + 8) * N_ + cb];
            *(float2*)y0 = make_float2(acc[mi][ni][0] + bs0, acc[mi][ni][1] + bs0);
            *(float2*)y1 = make_float2(acc[mi][ni][2] + bs1, acc[mi][ni][3] + bs1);
        }
    }
}

__global__ __launch_bounds__(128) void gemm_proj(
        const float* __restrict__ Wt, const float* __restrict__ bias,
        const float* __restrict__ X, float* __restrict__ Y) {
    __shared__ float Ws[16][72], Xs[16][72];
    int b = blockIdx.z;
    gemm_tile_tf32(Wt, bias, X + (size_t)b * C_ * N_, Y + (size_t)b * C_ * N_,
                   blockIdx.x << 6, blockIdx.y << 6, Ws, Xs);
}

__global__ __launch_bounds__(128) void gemm_kv(
        const float* __restrict__ Wk, const float* __restrict__ bk,
        const float* __restrict__ Wv, const float* __restrict__ bv,
        const float* __restrict__ X, float* __restrict__ Yk, float* __restrict__ Yv) {
    __shared__ float Ws[16][72], Xs[16][72];
    int z = blockIdx.z;
    int b = z >> 1, sel = z & 1;
    gemm_tile_tf32(sel ? Wv : Wk, sel ? bv : bk,
                   X + (size_t)b * C_ * N_, (sel ? Yv : Yk) + (size_t)b * C_ * N_,
                   blockIdx.x << 6, blockIdx.y << 6, Ws, Xs);
}

// ============================================================
// Offset network: 4 lanes per pixel, 16 channels each;
// LN stats + pointwise sums via quad shuffles.
// ============================================================
__global__ __launch_bounds__(256) void offset_kernel(
        const float* __restrict__ dw_w, const float* __restrict__ dw_b,
        const float* __restrict__ ln_w, const float* __restrict__ ln_b,
        const float* __restrict__ pw_w) {
    int t = blockIdx.x * blockDim.x + threadIdx.x;   // BG_*N_*4 threads
    int pix = t >> 2, q = t & 3;
    int bg = pix >> 10, p = pix & (N_ - 1);
    int h = p >> 5, w = p & 31;
    int b = bg >> 2, g = bg & 3;
    const float* qbase = g_q + (size_t)b * C_ * N_ + (size_t)g * GC_ * N_
                       + (size_t)q * 16 * N_;

    float x[16];
    float s1 = 0.f;
#pragma unroll
    for (int j = 0; j < 16; j++) {
        int c = q * 16 + j;
        const float* qc = qbase + j * N_;
        float tt = dw_b[c];
#pragma unroll
        for (int dy = 0; dy < 3; dy++) {
            int hh = h + dy - 1;
            if (hh < 0 || hh >= H_) continue;
#pragma unroll
            for (int dx = 0; dx < 3; dx++) {
                int ww = w + dx - 1;
                if (ww < 0 || ww >= W_) continue;
                tt += dw_w[c * 9 + dy * 3 + dx] * qc[hh * W_ + ww];
            }
        }
        x[j] = tt; s1 += tt;
    }
    s1 += __shfl_xor_sync(0xffffffffu, s1, 1);
    s1 += __shfl_xor_sync(0xffffffffu, s1, 2);
    float mu = s1 * (1.f / GC_);
    float s2 = 0.f;
#pragma unroll
    for (int j = 0; j < 16; j++) { float d = x[j] - mu; s2 += d * d; }
    s2 += __shfl_xor_sync(0xffffffffu, s2, 1);
    s2 += __shfl_xor_sync(0xffffffffu, s2, 2);
    float rinv = rsqrtf(s2 * (1.f / GC_) + EPS_);
    float off0 = 0.f, off1 = 0.f;
#pragma unroll
    for (int j = 0; j < 16; j++) {
        int c = q * 16 + j;
        float xn  = (x[j] - mu) * rinv * ln_w[c] + ln_b[c];
        float gel = 0.5f * xn * (1.f + erff(xn * 0.7071067811865476f));
        off0 += pw_w[c] * gel;          // y
        off1 += pw_w[GC_ + c] * gel;    // x
    }
    off0 += __shfl_xor_sync(0xffffffffu, off0, 1);
    off0 += __shfl_xor_sync(0xffffffffu, off0, 2);
    off1 += __shfl_xor_sync(0xffffffffu, off1, 1);
    off1 += __shfl_xor_sync(0xffffffffu, off1, 2);
    if (q == 0) {
        const float rng = 4.0f / 31.0f;
        float py = tanhf(off0) * rng + ((0.5f + (float)h) / 31.f) * 2.f - 1.f;
        float px = tanhf(off1) * rng + ((0.5f + (float)w) / 31.f) * 2.f - 1.f;
        g_pos[pix * 2 + 0] = py;
        g_pos[pix * 2 + 1] = px;
    }
}

// ============================================================
// Deformable bilinear sampling of kv features
// ============================================================
__global__ void sample_kernel(const float* __restrict__ kv) {
    int blk = blockIdx.x;                 // bg*N + p
    int c = threadIdx.x;
    int bg = blk >> 10, p = blk & (N_ - 1);
    int b = bg >> 2, g = bg & 3;
    float py = g_pos[blk * 2 + 0], px = g_pos[blk * 2 + 1];
    float ix = (px + 1.f) * 15.5f;
    float iy = (py + 1.f) * 15.5f;
    float x0f = floorf(ix), y0f = floorf(iy);
    float wx1 = ix - x0f, wx0 = 1.f - wx1;
    float wy1 = iy - y0f, wy0 = 1.f - wy1;
    int x0 = (int)x0f, y0 = (int)y0f;
    const float* src = kv + ((size_t)b * C_ + g * GC_ + c) * N_;
    float acc = 0.f;
#pragma unroll
    for (int cy = 0; cy < 2; cy++) {
        int yy = y0 + cy;
        if (yy < 0 || yy >= H_) continue;
        float wy = cy ? wy1 : wy0;
#pragma unroll
        for (int cx = 0; cx < 2; cx++) {
            int xx = x0 + cx;
            if (xx < 0 || xx >= W_) continue;
            acc += wy * (cx ? wx1 : wx0) * src[yy * W_ + xx];
        }
    }
    g_xs[((size_t)b * C_ + g * GC_ + c) * N_ + p] = acc;
}

// ============================================================
// Fused flash attention on tensor cores (3xTF32).
// 256 threads = 8 warps; one 128-row m-tile per block;
// warp w owns m-rows [w*16, w*16+16).
// K/V tf32 splits precomputed cooperatively into smem (8x dedup);
// per-n bias weights precomputed per n-tile.
// ============================================================
#define FL_KHI 0
#define FL_KLO 8704
#define FL_VHI 17408
#define FL_VLO 26112
#define FL_PS  34816           /* 128*68*4 = 34816 */
#define FL_TB  69632           /* 69*69*4 = 19044 -> pad 19072 */
#define FL_W4  88704           /* 64 * float4 */
#define FL_IB  89728           /* 64 * int */
#define FL_SMEM 89984

__global__ __launch_bounds__(256) void flash_kernel(const float* __restrict__ rpe) {
    extern __shared__ char sm_[];
    float*  khi = (float*)(sm_ + FL_KHI);   // [32][68] tf32-hi of K
    float*  klo = (float*)(sm_ + FL_KLO);   // [32][68] tf32-lo of K
    float*  vhi = (float*)(sm_ + FL_VHI);   // [32][68] tf32-hi of V
    float*  vlo = (float*)(sm_ + FL_VLO);   // [32][68] tf32-lo of V
    float*  ps  = (float*)(sm_ + FL_PS);    // [128][68] P / O^T
    float*  tb  = (float*)(sm_ + FL_TB);    // [69][69] zero-padded rpe table
    float4* w4  = (float4*)(sm_ + FL_W4);   // per-n bilinear weights
    int*    ib  = (int*)(sm_ + FL_IB);      // per-n table base index

    int tid = threadIdx.x;
    int lane = tid & 31, wid = tid >> 5;
    int gid = lane >> 2, tig = lane & 3;
    int wm = wid << 4;                      // warp m-offset in 128-row tile
    int bh = blockIdx.y, b = bh >> 3, hd = bh & 7;
    int m0 = blockIdx.x << 7;

    const float* qb = g_q + (size_t)(b * C_ + hd * HC_) * N_;
    const float* kb = g_k + (size_t)(b * C_ + hd * HC_) * N_;
    const float* vb = g_v + (size_t)(b * C_ + hd * HC_) * N_;
    const float* posb = g_pos + (size_t)(b * NG_ + (hd >> 1)) * N_ * 2;
    const float* tsrc = rpe + hd * 3969;

    // zero padded table then fill interior at [3][3]
    for (int i = tid; i < 69 * 69; i += 256) tb[i] = 0.f;
    __syncthreads();
    for (int i = tid; i < 3969; i += 256) {
        int y = i / 63, x = i - y * 63;
        tb[(y + 3) * 69 + x + 3] = tsrc[i];
    }

    // Q fragments (loop-invariant): rows mA, mA+8; cols kc*8+tig(+4)
    int mA = m0 + wm + gid;
    unsigned qhi[4][4], qlo[4][4];
#pragma unroll
    for (int kc = 0; kc < 4; kc++) {
        int c0 = (kc << 3) + tig;
        float a0 = qb[(size_t)c0 * N_ + mA] * SCALE_;
        float a1 = qb[(size_t)c0 * N_ + mA + 8] * SCALE_;
        float a2 = qb[(size_t)(c0 + 4) * N_ + mA] * SCALE_;
        float a3 = qb[(size_t)(c0 + 4) * N_ + mA + 8] * SCALE_;
        split_tf32(a0, qhi[kc][0], qlo[kc][0]);
        split_tf32(a1, qhi[kc][1], qlo[kc][1]);
        split_tf32(a2, qhi[kc][2], qlo[kc][2]);
        split_tf32(a3, qhi[kc][3], qlo[kc][3]);
    }

    int moff0 = (mA >> 5) * 69 + (mA & 31);
    int moff1 = ((mA + 8) >> 5) * 69 + ((mA + 8) & 31);

    float runm0 = -1e30f, runm1 = -1e30f;
    float rsum0 = 0.f, rsum1 = 0.f;
    float oacc[4][4] = {};

    for (int nt = 0; nt < 16; nt++) {
        int n0 = nt << 6;
        __syncthreads();                    // prior PV reads done
        // stage K/V with precomputed tf32 splits (cooperative, 8x dedup)
        for (int i = tid; i < 512; i += 256) {
            int c = i >> 4, col = (i & 15) << 2;
            float4 kk = *(const float4*)&kb[(size_t)c * N_ + n0 + col];
            float4 vv = *(const float4*)&vb[(size_t)c * N_ + n0 + col];
            unsigned h0, l0, h1, l1, h2, l2, h3, l3;
            split_tf32(kk.x, h0, l0); split_tf32(kk.y, h1, l1);
            split_tf32(kk.z, h2, l2); split_tf32(kk.w, h3, l3);
            *(float4*)&khi[c * 68 + col] = make_float4(
                __uint_as_float(h0), __uint_as_float(h1),
                __uint_as_float(h2), __uint_as_float(h3));
            *(float4*)&klo[c * 68 + col] = make_float4(
                __uint_as_float(l0), __uint_as_float(l1),
                __uint_as_float(l2), __uint_as_float(l3));
            split_tf32(vv.x, h0, l0); split_tf32(vv.y, h1, l1);
            split_tf32(vv.z, h2, l2); split_tf32(vv.w, h3, l3);
            *(float4*)&vhi[c * 68 + col] = make_float4(
                __uint_as_float(h0), __uint_as_float(h1),
                __uint_as_float(h2), __uint_as_float(h3));
            *(float4*)&vlo[c * 68 + col] = make_float4(
                __uint_as_float(l0), __uint_as_float(l1),
                __uint_as_float(l2), __uint_as_float(l3));
        }
        // per-n bilinear weights + base index
        if (tid < 64) {
            float biy = 15.5f - 15.5f * posb[(n0 + tid) * 2 + 0];
            float bix = 15.5f - 15.5f * posb[(n0 + tid) * 2 + 1];
            float fy = floorf(biy), fx = floorf(bix);
            float wy1 = biy - fy, wx1 = bix - fx;
            float wy0 = 1.f - wy1, wx0 = 1.f - wx1;
            w4[tid] = make_float4(wy0 * wx0, wy0 * wx1, wy1 * wx0, wy1 * wx1);
            ib[tid] = ((int)fy + 3) * 69 + (int)fx + 3;
        }
        __syncthreads();

        // ---- S = Q^T K (3xTF32 mma; B-frags are 2 LDS each) ----
        float sacc[8][4] = {};
#pragma unroll
        for (int kc = 0; kc < 4; kc++) {
            int r0 = ((kc << 3) + tig) * 68;
            int r1 = r0 + 4 * 68;
#pragma unroll
            for (int j = 0; j < 8; j++) {
                int nn = (j << 3) + gid;
                unsigned bh2[2] = { __float_as_uint(khi[r0 + nn]),
                                    __float_as_uint(khi[r1 + nn]) };
                unsigned bl2[2] = { __float_as_uint(klo[r0 + nn]),
                                    __float_as_uint(klo[r1 + nn]) };
                mma_tf32(sacc[j], qhi[kc], bh2);
                mma_tf32(sacc[j], qhi[kc], bl2);
                mma_tf32(sacc[j], qlo[kc], bh2);
            }
        }

        // ---- + rpe bias (precomputed per-n weights) ----
#pragma unroll
        for (int j = 0; j < 8; j++) {
#pragma unroll
            for (int e = 0; e < 2; e++) {
                int nn = (j << 3) + (tig << 1) + e;
                float4 w = w4[nn];
                int idxb = ib[nn];
                int ia = idxb + moff0;
                sacc[j][e] += w.x * tb[ia] + w.y * tb[ia + 1]
                            + w.z * tb[ia + 69] + w.w * tb[ia + 70];
                int ic = idxb + moff1;
                sacc[j][2 + e] += w.x * tb[ic] + w.y * tb[ic + 1]
                                + w.z * tb[ic + 69] + w.w * tb[ic + 70];
            }
        }

        // ---- online softmax (rows mA, mA+8; quad shuffles) ----
        float tm0 = -1e30f, tm1 = -1e30f;
#pragma unroll
        for (int j = 0; j < 8; j++) {
            tm0 = fmaxf(tm0, fmaxf(sacc[j][0], sacc[j][1]));
            tm1 = fmaxf(tm1, fmaxf(sacc[j][2], sacc[j][3]));
        }
        tm0 = fmaxf(tm0, __shfl_xor_sync(0xffffffffu, tm0, 1));
        tm0 = fmaxf(tm0, __shfl_xor_sync(0xffffffffu, tm0, 2));
        tm1 = fmaxf(tm1, __shfl_xor_sync(0xffffffffu, tm1, 1));
        tm1 = fmaxf(tm1, __shfl_xor_sync(0xffffffffu, tm1, 2));
        float nm0 = fmaxf(runm0, tm0), nm1 = fmaxf(runm1, tm1);
        float corr0 = __expf(runm0 - nm0), corr1 = __expf(runm1 - nm1);
        runm0 = nm0; runm1 = nm1;
        float lsum0 = 0.f, lsum1 = 0.f;
        int pr0 = (wm + gid) * 68 + (tig << 1);
        int pr1 = (wm + gid + 8) * 68 + (tig << 1);
#pragma unroll
        for (int j = 0; j < 8; j++) {
            float p0 = __expf(sacc[j][0] - nm0);
            float p1 = __expf(sacc[j][1] - nm0);
            float p2 = __expf(sacc[j][2] - nm1);
            float p3 = __expf(sacc[j][3] - nm1);
            lsum0 += p0 + p1; lsum1 += p2 + p3;
            *(float2*)&ps[pr0 + (j << 3)] = make_float2(p0, p1);
            *(float2*)&ps[pr1 + (j << 3)] = make_float2(p2, p3);
        }
        rsum0 = rsum0 * corr0 + lsum0;
        rsum1 = rsum1 * corr1 + lsum1;
#pragma unroll
        for (int ct = 0; ct < 4; ct++) {
            oacc[ct][0] *= corr0; oacc[ct][1] *= corr0;
            oacc[ct][2] *= corr1; oacc[ct][3] *= corr1;
        }
        __syncwarp();   // P rows are warp-private

        // ---- O += P V (A=P split in regs; B=V from precomputed splits) ----
#pragma unroll
        for (int kc = 0; kc < 8; kc++) {
            int kcol = (kc << 3) + tig;
            unsigned ah[4], al[4];
            split_tf32(ps[(wm + gid) * 68 + kcol],         ah[0], al[0]);
            split_tf32(ps[(wm + gid + 8) * 68 + kcol],     ah[1], al[1]);
            split_tf32(ps[(wm + gid) * 68 + kcol + 4],     ah[2], al[2]);
            split_tf32(ps[(wm + gid + 8) * 68 + kcol + 4], ah[3], al[3]);
#pragma unroll
            for (int ct = 0; ct < 4; ct++) {
                int vrow = ((ct << 3) + gid) * 68 + kcol;
                unsigned bh2[2] = { __float_as_uint(vhi[vrow]),
                                    __float_as_uint(vhi[vrow + 4]) };
                unsigned bl2[2] = { __float_as_uint(vlo[vrow]),
                                    __float_as_uint(vlo[vrow + 4]) };
                mma_tf32(oacc[ct], ah, bh2);
                mma_tf32(oacc[ct], ah, bl2);
                mma_tf32(oacc[ct], al, bh2);
            }
        }
    }

    // final row sums (quad reduce), normalize, write via smem transpose
    rsum0 += __shfl_xor_sync(0xffffffffu, rsum0, 1);
    rsum0 += __shfl_xor_sync(0xffffffffu, rsum0, 2);
    rsum1 += __shfl_xor_sync(0xffffffffu, rsum1, 1);
    rsum1 += __shfl_xor_sync(0xffffffffu, rsum1, 2);
    float inv0 = 1.f / rsum0, inv1 = 1.f / rsum1;

    __syncthreads();   // everyone done reading ps as P
#pragma unroll
    for (int ct = 0; ct < 4; ct++) {
        int cc = (ct << 3) + (tig << 1);
        *(float2*)&ps[(wm + gid) * 68 + cc] =
            make_float2(oacc[ct][0] * inv0, oacc[ct][1] * inv0);
        *(float2*)&ps[(wm + gid + 8) * 68 + cc] =
            make_float2(oacc[ct][2] * inv1, oacc[ct][3] * inv1);
    }
    __syncthreads();
    float* ob = g_o + (size_t)(b * C_ + hd * HC_) * N_;
    for (int i = tid; i < 4096; i += 256) {
        int c = i >> 7, m = i & 127;
        ob[(size_t)c * N_ + m0 + m] = ps[m * 68 + c];
    }
}

// ============================================================
extern "C" void kernel_launch(void* const* d_in, const int* in_sizes, int n_in,
                              void* d_out, int out_size) {
    const float* q_feat = (const float*)d_in[0];
    const float* kv_feat = (const float*)d_in[1];
    const float* Wq = (const float*)d_in[2];
    const float* bq = (const float*)d_in[3];
    const float* Wk = (const float*)d_in[4];
    const float* bk = (const float*)d_in[5];
    const float* Wv = (const float*)d_in[6];
    const float* bv = (const float*)d_in[7];
    const float* Wo = (const float*)d_in[8];
    const float* bo = (const float*)d_in[9];
    const float* dw_w = (const float*)d_in[10];
    const float* dw_b = (const float*)d_in[11];
    const float* ln_w = (const float*)d_in[12];
    const float* ln_b = (const float*)d_in[13];
    const float* pw_w = (const float*)d_in[14];
    const float* rpe  = (const float*)d_in[15];
    float* out = (float*)d_out;

    float *gq, *gxs, *gk, *gv, *go;
    cudaGetSymbolAddress((void**)&gq,  g_q);
    cudaGetSymbolAddress((void**)&gxs, g_xs);
    cudaGetSymbolAddress((void**)&gk,  g_k);
    cudaGetSymbolAddress((void**)&gv,  g_v);
    cudaGetSymbolAddress((void**)&go,  g_o);

    static int smem_set = 0;
    if (!smem_set) {
        cudaFuncSetAttribute(flash_kernel,
                             cudaFuncAttributeMaxDynamicSharedMemorySize, FL_SMEM);
        smem_set = 1;
    }

    dim3 gemm_grid(N_ / 64, C_ / 64, B_);
    dim3 kv_grid(N_ / 64, C_ / 64, B_ * 2);

    gemm_proj<<<gemm_grid, 128>>>(Wq, bq, q_feat, gq);
    offset_kernel<<<(BG_ * N_ * 4) / 256, 256>>>(dw_w, dw_b, ln_w, ln_b, pw_w);
    sample_kernel<<<BG_ * N_, GC_>>>(kv_feat);
    gemm_kv<<<kv_grid, 128>>>(Wk, bk, Wv, bv, gxs, gk, gv);
    flash_kernel<<<dim3(N_ / 128, B_ * NH_), 256, FL_SMEM>>>(rpe);
    gemm_proj<<<gemm_grid, 128>>>(Wo, bo, go, out);
}

// round 14
// speedup vs baseline: 1.1718x; 1.1718x over previous
#include <cuda_runtime.h>
#include <math.h>

#define B_   4
#define C_   256
#define H_   32
#define W_   32
#define N_   1024
#define NH_  8
#define HC_  32
#define NG_  4
#define GC_  64
#define BG_  16
#define SCALE_ 0.17677669529663687f   /* 32^-0.5 */
#define EPS_  1e-5f

// ---- scratch (device globals; no allocations allowed) ----
__device__ float g_q  [B_*C_*N_];
__device__ float g_pos[BG_*N_*2];
__device__ float g_xs [B_*C_*N_];
__device__ float g_k  [B_*C_*N_];
__device__ float g_v  [B_*C_*N_];
__device__ float g_o  [B_*C_*N_];

// ---- tf32 mma helpers (3xTF32 error-compensated path) ----
__device__ __forceinline__ unsigned cvt_tf32(float x) {
    unsigned r; asm("cvt.rna.tf32.f32 %0, %1;" : "=r"(r) : "f"(x)); return r;
}
__device__ __forceinline__ void split_tf32(float x, unsigned& hi, unsigned& lo) {
    hi = cvt_tf32(x);
    lo = cvt_tf32(x - __uint_as_float(hi));
}
__device__ __forceinline__ void mma_tf32(float* d, const unsigned* a, const unsigned* b) {
    asm("mma.sync.aligned.m16n8k8.row.col.f32.tf32.tf32.f32 "
        "{%0,%1,%2,%3}, {%4,%5,%6,%7}, {%8,%9}, {%0,%1,%2,%3};"
        : "+f"(d[0]), "+f"(d[1]), "+f"(d[2]), "+f"(d[3])
        : "r"(a[0]), "r"(a[1]), "r"(a[2]), "r"(a[3]), "r"(b[0]), "r"(b[1]));
}

// ============================================================
// Projection GEMM via 3xTF32 tensor mma.
// hi/lo splits precomputed at staging (once per value, off the
// mma dependency chain); inner loop is pure LDS + MMA.
// ============================================================
__device__ __forceinline__ void gemm_tile_tf32(
        const float* __restrict__ Wt, const float* __restrict__ bias,
        const float* __restrict__ Xb, float* __restrict__ Yb,
        int p0, int o0,
        float (*Wh)[72], float (*Wl)[72], float (*Xh)[72], float (*Xl)[72]) {
    int tid = threadIdx.x;
    int lane = tid & 31, wid = tid >> 5;
    int gid = lane >> 2, tig = lane & 3;
    int wm0 = (wid >> 1) << 5;
    int wn0 = (wid & 1) << 5;

    float acc[2][4][4] = {};

    for (int kt = 0; kt < C_; kt += 16) {
        // stage W^T slab pre-split: Wh/Wl[k][o]
        {
            int o = tid >> 1, kq = (tid & 1) << 3;
            const float* wp = &Wt[(size_t)(o0 + o) * C_ + kt + kq];
            float4 wa = *(const float4*)wp;
            float4 wb = *(const float4*)(wp + 4);
            unsigned h, l;
            split_tf32(wa.x, h, l); Wh[kq + 0][o] = __uint_as_float(h); Wl[kq + 0][o] = __uint_as_float(l);
            split_tf32(wa.y, h, l); Wh[kq + 1][o] = __uint_as_float(h); Wl[kq + 1][o] = __uint_as_float(l);
            split_tf32(wa.z, h, l); Wh[kq + 2][o] = __uint_as_float(h); Wl[kq + 2][o] = __uint_as_float(l);
            split_tf32(wa.w, h, l); Wh[kq + 3][o] = __uint_as_float(h); Wl[kq + 3][o] = __uint_as_float(l);
            split_tf32(wb.x, h, l); Wh[kq + 4][o] = __uint_as_float(h); Wl[kq + 4][o] = __uint_as_float(l);
            split_tf32(wb.y, h, l); Wh[kq + 5][o] = __uint_as_float(h); Wl[kq + 5][o] = __uint_as_float(l);
            split_tf32(wb.z, h, l); Wh[kq + 6][o] = __uint_as_float(h); Wl[kq + 6][o] = __uint_as_float(l);
            split_tf32(wb.w, h, l); Wh[kq + 7][o] = __uint_as_float(h); Wl[kq + 7][o] = __uint_as_float(l);
        }
        // stage X slab pre-split: Xh/Xl[k][p]
#pragma unroll
        for (int it = 0; it < 2; it++) {
            int i4 = tid + (it << 7);
            int k = i4 >> 4, p = (i4 & 15) << 2;
            float4 xv = *(const float4*)&Xb[(size_t)(kt + k) * N_ + p0 + p];
            unsigned h0, l0, h1, l1, h2, l2, h3, l3;
            split_tf32(xv.x, h0, l0); split_tf32(xv.y, h1, l1);
            split_tf32(xv.z, h2, l2); split_tf32(xv.w, h3, l3);
            *(float4*)&Xh[k][p] = make_float4(__uint_as_float(h0), __uint_as_float(h1),
                                              __uint_as_float(h2), __uint_as_float(h3));
            *(float4*)&Xl[k][p] = make_float4(__uint_as_float(l0), __uint_as_float(l1),
                                              __uint_as_float(l2), __uint_as_float(l3));
        }
        __syncthreads();

#pragma unroll
        for (int ks = 0; ks < 16; ks += 8) {
            unsigned ah[2][4], al[2][4], bh[4][2], bl[4][2];
#pragma unroll
            for (int mi = 0; mi < 2; mi++) {
                int r = wm0 + (mi << 4) + gid;
                ah[mi][0] = __float_as_uint(Wh[ks + tig][r]);
                al[mi][0] = __float_as_uint(Wl[ks + tig][r]);
                ah[mi][1] = __float_as_uint(Wh[ks + tig][r + 8]);
                al[mi][1] = __float_as_uint(Wl[ks + tig][r + 8]);
                ah[mi][2] = __float_as_uint(Wh[ks + tig + 4][r]);
                al[mi][2] = __float_as_uint(Wl[ks + tig + 4][r]);
                ah[mi][3] = __float_as_uint(Wh[ks + tig + 4][r + 8]);
                al[mi][3] = __float_as_uint(Wl[ks + tig + 4][r + 8]);
            }
#pragma unroll
            for (int ni = 0; ni < 4; ni++) {
                int cc = wn0 + (ni << 3) + gid;
                bh[ni][0] = __float_as_uint(Xh[ks + tig][cc]);
                bl[ni][0] = __float_as_uint(Xl[ks + tig][cc]);
                bh[ni][1] = __float_as_uint(Xh[ks + tig + 4][cc]);
                bl[ni][1] = __float_as_uint(Xl[ks + tig + 4][cc]);
            }
#pragma unroll
            for (int mi = 0; mi < 2; mi++)
#pragma unroll
                for (int ni = 0; ni < 4; ni++) {
                    mma_tf32(acc[mi][ni], ah[mi], bh[ni]);
                    mma_tf32(acc[mi][ni], ah[mi], bl[ni]);
                    mma_tf32(acc[mi][ni], al[mi], bh[ni]);
                }
        }
        __syncthreads();
    }

#pragma unroll
    for (int mi = 0; mi < 2; mi++) {
        int r = wm0 + (mi << 4) + gid;
        float bs0 = bias[o0 + r], bs1 = bias[o0 + r + 8];
#pragma unroll
        for (int ni = 0; ni < 4; ni++) {
            int cb = p0 + wn0 + (ni << 3) + (tig << 1);
            float* y0 = &Yb[(size_t)(o0 + r) * N_ + cb];
            float* y1 = &Yb[(size_t)(o0 + r + 8) * N_ + cb];
            *(float2*)y0 = make_float2(acc[mi][ni][0] + bs0, acc[mi][ni][1] + bs0);
            *(float2*)y1 = make_float2(acc[mi][ni][2] + bs1, acc[mi][ni][3] + bs1);
        }
    }
}

__global__ __launch_bounds__(128) void gemm_proj(
        const float* __restrict__ Wt, const float* __restrict__ bias,
        const float* __restrict__ X, float* __restrict__ Y) {
    __shared__ float Wh[16][72], Wl[16][72], Xh[16][72], Xl[16][72];
    int b = blockIdx.z;
    gemm_tile_tf32(Wt, bias, X + (size_t)b * C_ * N_, Y + (size_t)b * C_ * N_,
                   blockIdx.x << 6, blockIdx.y << 6, Wh, Wl, Xh, Xl);
}

__global__ __launch_bounds__(128) void gemm_kv(
        const float* __restrict__ Wk, const float* __restrict__ bk,
        const float* __restrict__ Wv, const float* __restrict__ bv,
        const float* __restrict__ X, float* __restrict__ Yk, float* __restrict__ Yv) {
    __shared__ float Wh[16][72], Wl[16][72], Xh[16][72], Xl[16][72];
    int z = blockIdx.z;
    int b = z >> 1, sel = z & 1;
    gemm_tile_tf32(sel ? Wv : Wk, sel ? bv : bk,
                   X + (size_t)b * C_ * N_, (sel ? Yv : Yk) + (size_t)b * C_ * N_,
                   blockIdx.x << 6, blockIdx.y << 6, Wh, Wl, Xh, Xl);
}

// ============================================================
// Offset network: 4 lanes per pixel, 16 channels each;
// LN stats + pointwise sums via quad shuffles.
// ============================================================
__global__ __launch_bounds__(256) void offset_kernel(
        const float* __restrict__ dw_w, const float* __restrict__ dw_b,
        const float* __restrict__ ln_w, const float* __restrict__ ln_b,
        const float* __restrict__ pw_w) {
    int t = blockIdx.x * blockDim.x + threadIdx.x;   // BG_*N_*4 threads
    int pix = t >> 2, q = t & 3;
    int bg = pix >> 10, p = pix & (N_ - 1);
    int h = p >> 5, w = p & 31;
    int b = bg >> 2, g = bg & 3;
    const float* qbase = g_q + (size_t)b * C_ * N_ + (size_t)g * GC_ * N_
                       + (size_t)q * 16 * N_;

    float x[16];
    float s1 = 0.f;
#pragma unroll
    for (int j = 0; j < 16; j++) {
        int c = q * 16 + j;
        const float* qc = qbase + j * N_;
        float tt = dw_b[c];
#pragma unroll
        for (int dy = 0; dy < 3; dy++) {
            int hh = h + dy - 1;
            if (hh < 0 || hh >= H_) continue;
#pragma unroll
            for (int dx = 0; dx < 3; dx++) {
                int ww = w + dx - 1;
                if (ww < 0 || ww >= W_) continue;
                tt += dw_w[c * 9 + dy * 3 + dx] * qc[hh * W_ + ww];
            }
        }
        x[j] = tt; s1 += tt;
    }
    s1 += __shfl_xor_sync(0xffffffffu, s1, 1);
    s1 += __shfl_xor_sync(0xffffffffu, s1, 2);
    float mu = s1 * (1.f / GC_);
    float s2 = 0.f;
#pragma unroll
    for (int j = 0; j < 16; j++) { float d = x[j] - mu; s2 += d * d; }
    s2 += __shfl_xor_sync(0xffffffffu, s2, 1);
    s2 += __shfl_xor_sync(0xffffffffu, s2, 2);
    float rinv = rsqrtf(s2 * (1.f / GC_) + EPS_);
    float off0 = 0.f, off1 = 0.f;
#pragma unroll
    for (int j = 0; j < 16; j++) {
        int c = q * 16 + j;
        float xn  = (x[j] - mu) * rinv * ln_w[c] + ln_b[c];
        float gel = 0.5f * xn * (1.f + erff(xn * 0.7071067811865476f));
        off0 += pw_w[c] * gel;          // y
        off1 += pw_w[GC_ + c] * gel;    // x
    }
    off0 += __shfl_xor_sync(0xffffffffu, off0, 1);
    off0 += __shfl_xor_sync(0xffffffffu, off0, 2);
    off1 += __shfl_xor_sync(0xffffffffu, off1, 1);
    off1 += __shfl_xor_sync(0xffffffffu, off1, 2);
    if (q == 0) {
        const float rng = 4.0f / 31.0f;
        float py = tanhf(off0) * rng + ((0.5f + (float)h) / 31.f) * 2.f - 1.f;
        float px = tanhf(off1) * rng + ((0.5f + (float)w) / 31.f) * 2.f - 1.f;
        g_pos[pix * 2 + 0] = py;
        g_pos[pix * 2 + 1] = px;
    }
}

// ============================================================
// Deformable bilinear sampling of kv features
// ============================================================
__global__ void sample_kernel(const float* __restrict__ kv) {
    int blk = blockIdx.x;                 // bg*N + p
    int c = threadIdx.x;
    int bg = blk >> 10, p = blk & (N_ - 1);
    int b = bg >> 2, g = bg & 3;
    float py = g_pos[blk * 2 + 0], px = g_pos[blk * 2 + 1];
    float ix = (px + 1.f) * 15.5f;
    float iy = (py + 1.f) * 15.5f;
    float x0f = floorf(ix), y0f = floorf(iy);
    float wx1 = ix - x0f, wx0 = 1.f - wx1;
    float wy1 = iy - y0f, wy0 = 1.f - wy1;
    int x0 = (int)x0f, y0 = (int)y0f;
    const float* src = kv + ((size_t)b * C_ + g * GC_ + c) * N_;
    float acc = 0.f;
#pragma unroll
    for (int cy = 0; cy < 2; cy++) {
        int yy = y0 + cy;
        if (yy < 0 || yy >= H_) continue;
        float wy = cy ? wy1 : wy0;
#pragma unroll
        for (int cx = 0; cx < 2; cx++) {
            int xx = x0 + cx;
            if (xx < 0 || xx >= W_) continue;
            acc += wy * (cx ? wx1 : wx0) * src[yy * W_ + xx];
        }
    }
    g_xs[((size_t)b * C_ + g * GC_ + c) * N_ + p] = acc;
}

// ============================================================
// Fused flash attention on tensor cores (3xTF32) — R12 structure:
// 128 threads = 4 warps, 64-row m-tile, warp w owns rows [w*16, w*16+16).
// Added: per-n bias weights/index precomputed per n-tile (w4/ib).
// ============================================================
#define FL_KS 0
#define FL_VS 8704
#define FL_PS 17408
#define FL_TB 34816            /* 69*69*4 = 19044 -> pad 19072 */
#define FL_W4 53888            /* 64 * float4 */
#define FL_IB 54912            /* 64 * int */
#define FL_SMEM 55168

__global__ __launch_bounds__(128) void flash_kernel(const float* __restrict__ rpe) {
    extern __shared__ char sm_[];
    float*  ks = (float*)(sm_ + FL_KS);    // [32][68]  k tile (c-major)
    float*  vs = (float*)(sm_ + FL_VS);    // [32][68]  v tile (c-major)
    float*  ps = (float*)(sm_ + FL_PS);    // [64][68]  P / O^T
    float*  tb = (float*)(sm_ + FL_TB);    // [69][69]  zero-padded rpe table
    float4* w4 = (float4*)(sm_ + FL_W4);   // per-n bilinear weights
    int*    ib = (int*)(sm_ + FL_IB);      // per-n table base index

    int tid = threadIdx.x;
    int lane = tid & 31, wid = tid >> 5;
    int gid = lane >> 2, tig = lane & 3;
    int wm = wid << 4;
    int bh = blockIdx.y, b = bh >> 3, hd = bh & 7;
    int m0 = blockIdx.x << 6;

    const float* qb = g_q + (size_t)(b * C_ + hd * HC_) * N_;
    const float* kb = g_k + (size_t)(b * C_ + hd * HC_) * N_;
    const float* vb = g_v + (size_t)(b * C_ + hd * HC_) * N_;
    const float* posb = g_pos + (size_t)(b * NG_ + (hd >> 1)) * N_ * 2;
    const float* tsrc = rpe + hd * 3969;

    for (int i = tid; i < 69 * 69; i += 128) tb[i] = 0.f;
    __syncthreads();
    for (int i = tid; i < 3969; i += 128) {
        int y = i / 63, x = i - y * 63;
        tb[(y + 3) * 69 + x + 3] = tsrc[i];
    }

    int mA = m0 + wm + gid;
    unsigned qhi[4][4], qlo[4][4];
#pragma unroll
    for (int kc = 0; kc < 4; kc++) {
        int c0 = (kc << 3) + tig;
        float a0 = qb[(size_t)c0 * N_ + mA] * SCALE_;
        float a1 = qb[(size_t)c0 * N_ + mA + 8] * SCALE_;
        float a2 = qb[(size_t)(c0 + 4) * N_ + mA] * SCALE_;
        float a3 = qb[(size_t)(c0 + 4) * N_ + mA + 8] * SCALE_;
        split_tf32(a0, qhi[kc][0], qlo[kc][0]);
        split_tf32(a1, qhi[kc][1], qlo[kc][1]);
        split_tf32(a2, qhi[kc][2], qlo[kc][2]);
        split_tf32(a3, qhi[kc][3], qlo[kc][3]);
    }

    int moff0 = (mA >> 5) * 69 + (mA & 31);
    int moff1 = ((mA + 8) >> 5) * 69 + ((mA + 8) & 31);

    float runm0 = -1e30f, runm1 = -1e30f;
    float rsum0 = 0.f, rsum1 = 0.f;
    float oacc[4][4] = {};

    for (int nt = 0; nt < 16; nt++) {
        int n0 = nt << 6;
        __syncthreads();
        for (int i = tid; i < 512; i += 128) {
            int c = i >> 4, col = (i & 15) << 2;
            *(float4*)&ks[c * 68 + col] = *(const float4*)&kb[(size_t)c * N_ + n0 + col];
            *(float4*)&vs[c * 68 + col] = *(const float4*)&vb[(size_t)c * N_ + n0 + col];
        }
        if (tid < 64) {
            float biy = 15.5f - 15.5f * posb[(n0 + tid) * 2 + 0];
            float bix = 15.5f - 15.5f * posb[(n0 + tid) * 2 + 1];
            float fy = floorf(biy), fx = floorf(bix);
            float wy1 = biy - fy, wx1 = bix - fx;
            float wy0 = 1.f - wy1, wx0 = 1.f - wx1;
            w4[tid] = make_float4(wy0 * wx0, wy0 * wx1, wy1 * wx0, wy1 * wx1);
            ib[tid] = ((int)fy + 3) * 69 + (int)fx + 3;
        }
        __syncthreads();

        // ---- S = Q^T K (3xTF32 mma) ----
        float sacc[8][4] = {};
#pragma unroll
        for (int kc = 0; kc < 4; kc++) {
            int r0 = ((kc << 3) + tig) * 68;
            int r1 = r0 + 4 * 68;
#pragma unroll
            for (int j = 0; j < 8; j++) {
                int nn = (j << 3) + gid;
                unsigned b0h, b0l, b1h, b1l;
                split_tf32(ks[r0 + nn], b0h, b0l);
                split_tf32(ks[r1 + nn], b1h, b1l);
                unsigned bh2[2] = {b0h, b1h}, bl2[2] = {b0l, b1l};
                mma_tf32(sacc[j], qhi[kc], bh2);
                mma_tf32(sacc[j], qhi[kc], bl2);
                mma_tf32(sacc[j], qlo[kc], bh2);
            }
        }

        // ---- + rpe bias (precomputed per-n weights) ----
#pragma unroll
        for (int j = 0; j < 8; j++) {
#pragma unroll
            for (int e = 0; e < 2; e++) {
                int nn = (j << 3) + (tig << 1) + e;
                float4 w = w4[nn];
                int idxb = ib[nn];
                int ia = idxb + moff0;
                sacc[j][e] += w.x * tb[ia] + w.y * tb[ia + 1]
                            + w.z * tb[ia + 69] + w.w * tb[ia + 70];
                int ic = idxb + moff1;
                sacc[j][2 + e] += w.x * tb[ic] + w.y * tb[ic + 1]
                                + w.z * tb[ic + 69] + w.w * tb[ic + 70];
            }
        }

        // ---- online softmax (rows mA, mA+8; quad shuffles) ----
        float tm0 = -1e30f, tm1 = -1e30f;
#pragma unroll
        for (int j = 0; j < 8; j++) {
            tm0 = fmaxf(tm0, fmaxf(sacc[j][0], sacc[j][1]));
            tm1 = fmaxf(tm1, fmaxf(sacc[j][2], sacc[j][3]));
        }
        tm0 = fmaxf(tm0, __shfl_xor_sync(0xffffffffu, tm0, 1));
        tm0 = fmaxf(tm0, __shfl_xor_sync(0xffffffffu, tm0, 2));
        tm1 = fmaxf(tm1, __shfl_xor_sync(0xffffffffu, tm1, 1));
        tm1 = fmaxf(tm1, __shfl_xor_sync(0xffffffffu, tm1, 2));
        float nm0 = fmaxf(runm0, tm0), nm1 = fmaxf(runm1, tm1);
        float corr0 = __expf(runm0 - nm0), corr1 = __expf(runm1 - nm1);
        runm0 = nm0; runm1 = nm1;
        float lsum0 = 0.f, lsum1 = 0.f;
        int pr0 = (wm + gid) * 68 + (tig << 1);
        int pr1 = (wm + gid + 8) * 68 + (tig << 1);
#pragma unroll
        for (int j = 0; j < 8; j++) {
            float p0 = __expf(sacc[j][0] - nm0);
            float p1 = __expf(sacc[j][1] - nm0);
            float p2 = __expf(sacc[j][2] - nm1);
            float p3 = __expf(sacc[j][3] - nm1);
            lsum0 += p0 + p1; lsum1 += p2 + p3;
            *(float2*)&ps[pr0 + (j << 3)] = make_float2(p0, p1);
            *(float2*)&ps[pr1 + (j << 3)] = make_float2(p2, p3);
        }
        rsum0 = rsum0 * corr0 + lsum0;
        rsum1 = rsum1 * corr1 + lsum1;
#pragma unroll
        for (int ct = 0; ct < 4; ct++) {
            oacc[ct][0] *= corr0; oacc[ct][1] *= corr0;
            oacc[ct][2] *= corr1; oacc[ct][3] *= corr1;
        }
        __syncwarp();

        // ---- O += P V (3xTF32 mma) ----
#pragma unroll
        for (int kc = 0; kc < 8; kc++) {
            int kcol = (kc << 3) + tig;
            unsigned ah[4], al[4];
            split_tf32(ps[(wm + gid) * 68 + kcol],         ah[0], al[0]);
            split_tf32(ps[(wm + gid + 8) * 68 + kcol],     ah[1], al[1]);
            split_tf32(ps[(wm + gid) * 68 + kcol + 4],     ah[2], al[2]);
            split_tf32(ps[(wm + gid + 8) * 68 + kcol + 4], ah[3], al[3]);
#pragma unroll
            for (int ct = 0; ct < 4; ct++) {
                int vrow = ((ct << 3) + gid) * 68 + kcol;
                unsigned b0h, b0l, b1h, b1l;
                split_tf32(vs[vrow],     b0h, b0l);
                split_tf32(vs[vrow + 4], b1h, b1l);
                unsigned bh2[2] = {b0h, b1h}, bl2[2] = {b0l, b1l};
                mma_tf32(oacc[ct], ah, bh2);
                mma_tf32(oacc[ct], ah, bl2);
                mma_tf32(oacc[ct], al, bh2);
            }
        }
    }

    rsum0 += __shfl_xor_sync(0xffffffffu, rsum0, 1);
    rsum0 += __shfl_xor_sync(0xffffffffu, rsum0, 2);
    rsum1 += __shfl_xor_sync(0xffffffffu, rsum1, 1);
    rsum1 += __shfl_xor_sync(0xffffffffu, rsum1, 2);
    float inv0 = 1.f / rsum0, inv1 = 1.f / rsum1;

    __syncthreads();
#pragma unroll
    for (int ct = 0; ct < 4; ct++) {
        int cc = (ct << 3) + (tig << 1);
        *(float2*)&ps[(wm + gid) * 68 + cc] =
            make_float2(oacc[ct][0] * inv0, oacc[ct][1] * inv0);
        *(float2*)&ps[(wm + gid + 8) * 68 + cc] =
            make_float2(oacc[ct][2] * inv1, oacc[ct][3] * inv1);
    }
    __syncthreads();
    float* ob = g_o + (size_t)(b * C_ + hd * HC_) * N_;
    for (int i = tid; i < 2048; i += 128) {
        int c = i >> 6, m = i & 63;
        ob[(size_t)c * N_ + m0 + m] = ps[m * 68 + c];
    }
}

// ============================================================
extern "C" void kernel_launch(void* const* d_in, const int* in_sizes, int n_in,
                              void* d_out, int out_size) {
    const float* q_feat = (const float*)d_in[0];
    const float* kv_feat = (const float*)d_in[1];
    const float* Wq = (const float*)d_in[2];
    const float* bq = (const float*)d_in[3];
    const float* Wk = (const float*)d_in[4];
    const float* bk = (const float*)d_in[5];
    const float* Wv = (const float*)d_in[6];
    const float* bv = (const float*)d_in[7];
    const float* Wo = (const float*)d_in[8];
    const float* bo = (const float*)d_in[9];
    const float* dw_w = (const float*)d_in[10];
    const float* dw_b = (const float*)d_in[11];
    const float* ln_w = (const float*)d_in[12];
    const float* ln_b = (const float*)d_in[13];
    const float* pw_w = (const float*)d_in[14];
    const float* rpe  = (const float*)d_in[15];
    float* out = (float*)d_out;

    float *gq, *gxs, *gk, *gv, *go;
    cudaGetSymbolAddress((void**)&gq,  g_q);
    cudaGetSymbolAddress((void**)&gxs, g_xs);
    cudaGetSymbolAddress((void**)&gk,  g_k);
    cudaGetSymbolAddress((void**)&gv,  g_v);
    cudaGetSymbolAddress((void**)&go,  g_o);

    static int smem_set = 0;
    if (!smem_set) {
        cudaFuncSetAttribute(flash_kernel,
                             cudaFuncAttributeMaxDynamicSharedMemorySize, FL_SMEM);
        smem_set = 1;
    }

    dim3 gemm_grid(N_ / 64, C_ / 64, B_);
    dim3 kv_grid(N_ / 64, C_ / 64, B_ * 2);

    gemm_proj<<<gemm_grid, 128>>>(Wq, bq, q_feat, gq);
    offset_kernel<<<(BG_ * N_ * 4) / 256, 256>>>(dw_w, dw_b, ln_w, ln_b, pw_w);
    sample_kernel<<<BG_ * N_, GC_>>>(kv_feat);
    gemm_kv<<<kv_grid, 128>>>(Wk, bk, Wv, bv, gxs, gk, gv);
    flash_kernel<<<dim3(N_ / 64, B_ * NH_), 128, FL_SMEM>>>(rpe);
    gemm_proj<<<gemm_grid, 128>>>(Wo, bo, go, out);
}

// round 15
// speedup vs baseline: 1.3758x; 1.1741x over previous
#include <cuda_runtime.h>
#include <math.h>

#define B_   4
#define C_   256
#define H_   32
#define W_   32
#define N_   1024
#define NH_  8
#define HC_  32
#define NG_  4
#define GC_  64
#define BG_  16
#define SCALE_ 0.17677669529663687f   /* 32^-0.5 */
#define EPS_  1e-5f

// ---- scratch (device globals; no allocations allowed) ----
__device__ float g_q  [B_*C_*N_];
__device__ float g_pos[BG_*N_*2];
__device__ float g_xs [B_*C_*N_];
__device__ float g_k  [B_*C_*N_];
__device__ float g_v  [B_*C_*N_];
__device__ float g_o  [B_*C_*N_];

// ---- bf16 split-pack helpers ----
// pack two floats (e0 -> low 16 bits, e1 -> high 16 bits) as bf16x2
__device__ __forceinline__ unsigned bpack(float e0, float e1) {
    unsigned r; asm("cvt.rn.bf16x2.f32 %0, %1, %2;" : "=r"(r) : "f"(e1), "f"(e0));
    return r;
}
// split a k-pair (x0 = lower k index) into bf16x2 hi and residual lo
__device__ __forceinline__ void bsplit2(float x0, float x1, unsigned& hi, unsigned& lo) {
    unsigned h = bpack(x0, x1);
    float h0 = __uint_as_float(h << 16);
    float h1 = __uint_as_float(h & 0xffff0000u);
    hi = h;
    lo = bpack(x0 - h0, x1 - h1);
}
__device__ __forceinline__ void mma_bf16(float* d, const unsigned* a, const unsigned* b) {
    asm("mma.sync.aligned.m16n8k16.row.col.f32.bf16.bf16.f32 "
        "{%0,%1,%2,%3}, {%4,%5,%6,%7}, {%8,%9}, {%0,%1,%2,%3};"
        : "+f"(d[0]), "+f"(d[1]), "+f"(d[2]), "+f"(d[3])
        : "r"(a[0]), "r"(a[1]), "r"(a[2]), "r"(a[3]), "r"(b[0]), "r"(b[1]));
}

// ============================================================
// Projection GEMM via 3-term bf16 m16n8k16 mma.
// Y[o,p] = sum_i W[o,i]*X[i,p] + bias[o]
// Block 64(o) x 64(p), 128 thr = 4 warps, warp tile 32x32.
// W/X staged as packed bf16x2 (k-pairs) hi/lo arrays.
// ============================================================
__device__ __forceinline__ void gemm_tile_bf16(
        const float* __restrict__ Wt, const float* __restrict__ bias,
        const float* __restrict__ Xb, float* __restrict__ Yb,
        int p0, int o0,
        unsigned (*Wh)[72], unsigned (*Wl)[72],
        unsigned (*Xh)[72], unsigned (*Xl)[72]) {
    int tid = threadIdx.x;
    int lane = tid & 31, wid = tid >> 5;
    int gid = lane >> 2, tig = lane & 3;
    int wm0 = (wid >> 1) << 5;
    int wn0 = (wid & 1) << 5;

    float acc[2][4][4] = {};

    for (int kt = 0; kt < C_; kt += 16) {
        // stage W slab: Wh/Wl[kp][o], kp = k-pair 0..8
        {
            int o = tid >> 1, kq = (tid & 1) << 3;
            const float* wp = &Wt[(size_t)(o0 + o) * C_ + kt + kq];
            float4 wa = *(const float4*)wp;
            float4 wb = *(const float4*)(wp + 4);
            int kp0 = (tid & 1) << 2;
            bsplit2(wa.x, wa.y, Wh[kp0 + 0][o], Wl[kp0 + 0][o]);
            bsplit2(wa.z, wa.w, Wh[kp0 + 1][o], Wl[kp0 + 1][o]);
            bsplit2(wb.x, wb.y, Wh[kp0 + 2][o], Wl[kp0 + 2][o]);
            bsplit2(wb.z, wb.w, Wh[kp0 + 3][o], Wl[kp0 + 3][o]);
        }
        // stage X slab: Xh/Xl[kp][p]
        {
            int kp = tid >> 4, p4 = (tid & 15) << 2;
            float4 xa = *(const float4*)&Xb[(size_t)(kt + 2 * kp) * N_ + p0 + p4];
            float4 xb = *(const float4*)&Xb[(size_t)(kt + 2 * kp + 1) * N_ + p0 + p4];
            unsigned h0, l0, h1, l1, h2, l2, h3, l3;
            bsplit2(xa.x, xb.x, h0, l0);
            bsplit2(xa.y, xb.y, h1, l1);
            bsplit2(xa.z, xb.z, h2, l2);
            bsplit2(xa.w, xb.w, h3, l3);
            *(uint4*)&Xh[kp][p4] = make_uint4(h0, h1, h2, h3);
            *(uint4*)&Xl[kp][p4] = make_uint4(l0, l1, l2, l3);
        }
        __syncthreads();

        unsigned ah[2][4], al[2][4], bh[4][2], bl[4][2];
#pragma unroll
        for (int mi = 0; mi < 2; mi++) {
            int r = wm0 + (mi << 4) + gid;
            ah[mi][0] = Wh[tig][r];     al[mi][0] = Wl[tig][r];
            ah[mi][1] = Wh[tig][r + 8]; al[mi][1] = Wl[tig][r + 8];
            ah[mi][2] = Wh[tig + 4][r];     al[mi][2] = Wl[tig + 4][r];
            ah[mi][3] = Wh[tig + 4][r + 8]; al[mi][3] = Wl[tig + 4][r + 8];
        }
#pragma unroll
        for (int ni = 0; ni < 4; ni++) {
            int cc = wn0 + (ni << 3) + gid;
            bh[ni][0] = Xh[tig][cc];     bl[ni][0] = Xl[tig][cc];
            bh[ni][1] = Xh[tig + 4][cc]; bl[ni][1] = Xl[tig + 4][cc];
        }
#pragma unroll
        for (int mi = 0; mi < 2; mi++)
#pragma unroll
            for (int ni = 0; ni < 4; ni++) {
                mma_bf16(acc[mi][ni], ah[mi], bh[ni]);
                mma_bf16(acc[mi][ni], ah[mi], bl[ni]);
                mma_bf16(acc[mi][ni], al[mi], bh[ni]);
            }
        __syncthreads();
    }

#pragma unroll
    for (int mi = 0; mi < 2; mi++) {
        int r = wm0 + (mi << 4) + gid;
        float bs0 = bias[o0 + r], bs1 = bias[o0 + r + 8];
#pragma unroll
        for (int ni = 0; ni < 4; ni++) {
            int cb = p0 + wn0 + (ni << 3) + (tig << 1);
            float* y0 = &Yb[(size_t)(o0 + r) * N_ + cb];
            float* y1 = &Yb[(size_t)(o0 + r + 8) * N_ + cb];
            *(float2*)y0 = make_float2(acc[mi][ni][0] + bs0, acc[mi][ni][1] + bs0);
            *(float2*)y1 = make_float2(acc[mi][ni][2] + bs1, acc[mi][ni][3] + bs1);
        }
    }
}

__global__ __launch_bounds__(128) void gemm_proj(
        const float* __restrict__ Wt, const float* __restrict__ bias,
        const float* __restrict__ X, float* __restrict__ Y) {
    __shared__ unsigned Wh[8][72], Wl[8][72], Xh[8][72], Xl[8][72];
    int b = blockIdx.z;
    gemm_tile_bf16(Wt, bias, X + (size_t)b * C_ * N_, Y + (size_t)b * C_ * N_,
                   blockIdx.x << 6, blockIdx.y << 6, Wh, Wl, Xh, Xl);
}

__global__ __launch_bounds__(128) void gemm_kv(
        const float* __restrict__ Wk, const float* __restrict__ bk,
        const float* __restrict__ Wv, const float* __restrict__ bv,
        const float* __restrict__ X, float* __restrict__ Yk, float* __restrict__ Yv) {
    __shared__ unsigned Wh[8][72], Wl[8][72], Xh[8][72], Xl[8][72];
    int z = blockIdx.z;
    int b = z >> 1, sel = z & 1;
    gemm_tile_bf16(sel ? Wv : Wk, sel ? bv : bk,
                   X + (size_t)b * C_ * N_, (sel ? Yv : Yk) + (size_t)b * C_ * N_,
                   blockIdx.x << 6, blockIdx.y << 6, Wh, Wl, Xh, Xl);
}

// ============================================================
// Offset network: 4 lanes per pixel, 16 channels each.
// ============================================================
__global__ __launch_bounds__(256) void offset_kernel(
        const float* __restrict__ dw_w, const float* __restrict__ dw_b,
        const float* __restrict__ ln_w, const float* __restrict__ ln_b,
        const float* __restrict__ pw_w) {
    int t = blockIdx.x * blockDim.x + threadIdx.x;
    int pix = t >> 2, q = t & 3;
    int bg = pix >> 10, p = pix & (N_ - 1);
    int h = p >> 5, w = p & 31;
    int b = bg >> 2, g = bg & 3;
    const float* qbase = g_q + (size_t)b * C_ * N_ + (size_t)g * GC_ * N_
                       + (size_t)q * 16 * N_;

    float x[16];
    float s1 = 0.f;
#pragma unroll
    for (int j = 0; j < 16; j++) {
        int c = q * 16 + j;
        const float* qc = qbase + j * N_;
        float tt = dw_b[c];
#pragma unroll
        for (int dy = 0; dy < 3; dy++) {
            int hh = h + dy - 1;
            if (hh < 0 || hh >= H_) continue;
#pragma unroll
            for (int dx = 0; dx < 3; dx++) {
                int ww = w + dx - 1;
                if (ww < 0 || ww >= W_) continue;
                tt += dw_w[c * 9 + dy * 3 + dx] * qc[hh * W_ + ww];
            }
        }
        x[j] = tt; s1 += tt;
    }
    s1 += __shfl_xor_sync(0xffffffffu, s1, 1);
    s1 += __shfl_xor_sync(0xffffffffu, s1, 2);
    float mu = s1 * (1.f / GC_);
    float s2 = 0.f;
#pragma unroll
    for (int j = 0; j < 16; j++) { float d = x[j] - mu; s2 += d * d; }
    s2 += __shfl_xor_sync(0xffffffffu, s2, 1);
    s2 += __shfl_xor_sync(0xffffffffu, s2, 2);
    float rinv = rsqrtf(s2 * (1.f / GC_) + EPS_);
    float off0 = 0.f, off1 = 0.f;
#pragma unroll
    for (int j = 0; j < 16; j++) {
        int c = q * 16 + j;
        float xn  = (x[j] - mu) * rinv * ln_w[c] + ln_b[c];
        float gel = 0.5f * xn * (1.f + erff(xn * 0.7071067811865476f));
        off0 += pw_w[c] * gel;
        off1 += pw_w[GC_ + c] * gel;
    }
    off0 += __shfl_xor_sync(0xffffffffu, off0, 1);
    off0 += __shfl_xor_sync(0xffffffffu, off0, 2);
    off1 += __shfl_xor_sync(0xffffffffu, off1, 1);
    off1 += __shfl_xor_sync(0xffffffffu, off1, 2);
    if (q == 0) {
        const float rng = 4.0f / 31.0f;
        float py = tanhf(off0) * rng + ((0.5f + (float)h) / 31.f) * 2.f - 1.f;
        float px = tanhf(off1) * rng + ((0.5f + (float)w) / 31.f) * 2.f - 1.f;
        g_pos[pix * 2 + 0] = py;
        g_pos[pix * 2 + 1] = px;
    }
}

// ============================================================
// Deformable bilinear sampling of kv features
// ============================================================
__global__ void sample_kernel(const float* __restrict__ kv) {
    int blk = blockIdx.x;
    int c = threadIdx.x;
    int bg = blk >> 10, p = blk & (N_ - 1);
    int b = bg >> 2, g = bg & 3;
    float py = g_pos[blk * 2 + 0], px = g_pos[blk * 2 + 1];
    float ix = (px + 1.f) * 15.5f;
    float iy = (py + 1.f) * 15.5f;
    float x0f = floorf(ix), y0f = floorf(iy);
    float wx1 = ix - x0f, wx0 = 1.f - wx1;
    float wy1 = iy - y0f, wy0 = 1.f - wy1;
    int x0 = (int)x0f, y0 = (int)y0f;
    const float* src = kv + ((size_t)b * C_ + g * GC_ + c) * N_;
    float acc = 0.f;
#pragma unroll
    for (int cy = 0; cy < 2; cy++) {
        int yy = y0 + cy;
        if (yy < 0 || yy >= H_) continue;
        float wy = cy ? wy1 : wy0;
#pragma unroll
        for (int cx = 0; cx < 2; cx++) {
            int xx = x0 + cx;
            if (xx < 0 || xx >= W_) continue;
            acc += wy * (cx ? wx1 : wx0) * src[yy * W_ + xx];
        }
    }
    g_xs[((size_t)b * C_ + g * GC_ + c) * N_ + p] = acc;
}

// ============================================================
// Fused flash attention, 3-term bf16 m16n8k16 mma.
// 128 thr = 4 warps, 64-row m-tile, warp w owns rows [w*16, w*16+16).
// K, V pre-split to packed bf16x2 hi/lo at staging (dedup 4x);
// P stored pre-split by producer; rpe table in smem bf16.
// ============================================================
#define FL_KHI 0                 /* [16][72] u32 = 4608 */
#define FL_KLO 4608
#define FL_VHI 9216              /* [32][40] u32 = 5120 */
#define FL_VLO 14336
#define FL_PHI 19456             /* [64][36] u32 = 9216 */
#define FL_PLO 28672
#define FL_TB  37888             /* ushort[69*69]=9522 -> 9536 */
#define FL_W4  47424             /* 64 * float4 */
#define FL_IB  48448             /* 64 * int */
#define FL_SMEM 48704

__global__ __launch_bounds__(128) void flash_kernel(const float* __restrict__ rpe) {
    extern __shared__ char sm_[];
    unsigned* khi = (unsigned*)(sm_ + FL_KHI);   // [16][72] k-pairs (c), cols n
    unsigned* klo = (unsigned*)(sm_ + FL_KLO);
    unsigned* vhi = (unsigned*)(sm_ + FL_VHI);   // [32][40] n-pairs, cols c
    unsigned* vlo = (unsigned*)(sm_ + FL_VLO);
    unsigned* phi = (unsigned*)(sm_ + FL_PHI);   // [64][36] n-pairs of P
    unsigned* plo = (unsigned*)(sm_ + FL_PLO);
    unsigned short* tbs = (unsigned short*)(sm_ + FL_TB);  // [69][69] bf16
    float4* w4 = (float4*)(sm_ + FL_W4);
    int*    ib = (int*)(sm_ + FL_IB);

    int tid = threadIdx.x;
    int lane = tid & 31, wid = tid >> 5;
    int gid = lane >> 2, tig = lane & 3;
    int wm = wid << 4;
    int bh = blockIdx.y, b = bh >> 3, hd = bh & 7;
    int m0 = blockIdx.x << 6;

    const float* qb = g_q + (size_t)(b * C_ + hd * HC_) * N_;
    const float* kb = g_k + (size_t)(b * C_ + hd * HC_) * N_;
    const float* vb = g_v + (size_t)(b * C_ + hd * HC_) * N_;
    const float* posb = g_pos + (size_t)(b * NG_ + (hd >> 1)) * N_ * 2;
    const float* tsrc = rpe + hd * 3969;

    // zero padded bf16 table then fill interior at [3][3] (round-to-nearest)
    for (int i = tid; i < 69 * 69; i += 128) tbs[i] = 0;
    __syncthreads();
    for (int i = tid; i < 3969; i += 128) {
        int y = i / 63, x = i - y * 63;
        unsigned u = __float_as_uint(tsrc[i]) + 0x8000u;
        tbs[(y + 3) * 69 + x + 3] = (unsigned short)(u >> 16);
    }

    // Q fragments: 2 k16-chunks over c, packed bf16 pairs
    int mA = m0 + wm + gid;
    unsigned qh[2][4], ql[2][4];
#pragma unroll
    for (int kc = 0; kc < 2; kc++) {
        int cA = (kc << 4) + (tig << 1);        // pair for a0/a1
        int cB = cA + 8;                        // pair for a2/a3
        float a00 = qb[(size_t)cA * N_ + mA] * SCALE_;
        float a01 = qb[(size_t)(cA + 1) * N_ + mA] * SCALE_;
        float a10 = qb[(size_t)cA * N_ + mA + 8] * SCALE_;
        float a11 = qb[(size_t)(cA + 1) * N_ + mA + 8] * SCALE_;
        float a20 = qb[(size_t)cB * N_ + mA] * SCALE_;
        float a21 = qb[(size_t)(cB + 1) * N_ + mA] * SCALE_;
        float a30 = qb[(size_t)cB * N_ + mA + 8] * SCALE_;
        float a31 = qb[(size_t)(cB + 1) * N_ + mA + 8] * SCALE_;
        bsplit2(a00, a01, qh[kc][0], ql[kc][0]);
        bsplit2(a10, a11, qh[kc][1], ql[kc][1]);
        bsplit2(a20, a21, qh[kc][2], ql[kc][2]);
        bsplit2(a30, a31, qh[kc][3], ql[kc][3]);
    }

    int moff0 = (mA >> 5) * 69 + (mA & 31);
    int moff1 = ((mA + 8) >> 5) * 69 + ((mA + 8) & 31);

    float runm0 = -1e30f, runm1 = -1e30f;
    float rsum0 = 0.f, rsum1 = 0.f;
    float oacc[4][4] = {};

    for (int nt = 0; nt < 16; nt++) {
        int n0 = nt << 6;
        __syncthreads();   // prior tile's mma reads done (iter 0: table fill done)

        // stage K pre-split: khi/klo[kp][n], kp = c-pair
        for (int i = tid; i < 256; i += 128) {
            int kp = i >> 4, n4 = (i & 15) << 2;
            float4 ka = *(const float4*)&kb[(size_t)(2 * kp) * N_ + n0 + n4];
            float4 kc = *(const float4*)&kb[(size_t)(2 * kp + 1) * N_ + n0 + n4];
            unsigned h0, l0, h1, l1, h2, l2, h3, l3;
            bsplit2(ka.x, kc.x, h0, l0);
            bsplit2(ka.y, kc.y, h1, l1);
            bsplit2(ka.z, kc.z, h2, l2);
            bsplit2(ka.w, kc.w, h3, l3);
            *(uint4*)&khi[kp * 72 + n4] = make_uint4(h0, h1, h2, h3);
            *(uint4*)&klo[kp * 72 + n4] = make_uint4(l0, l1, l2, l3);
        }
        // stage V pre-split transposed: vhi/vlo[np][c], np = n-pair
        for (int i = tid; i < 512; i += 128) {
            int c = i >> 4, n4 = (i & 15) << 2;
            float4 vv = *(const float4*)&vb[(size_t)c * N_ + n0 + n4];
            unsigned h, l;
            int np = n4 >> 1;
            bsplit2(vv.x, vv.y, h, l);
            vhi[np * 40 + c] = h; vlo[np * 40 + c] = l;
            bsplit2(vv.z, vv.w, h, l);
            vhi[(np + 1) * 40 + c] = h; vlo[(np + 1) * 40 + c] = l;
        }
        // per-n bilinear weights + base index
        if (tid < 64) {
            float biy = 15.5f - 15.5f * posb[(n0 + tid) * 2 + 0];
            float bix = 15.5f - 15.5f * posb[(n0 + tid) * 2 + 1];
            float fy = floorf(biy), fx = floorf(bix);
            float wy1 = biy - fy, wx1 = bix - fx;
            float wy0 = 1.f - wy1, wx0 = 1.f - wx1;
            w4[tid] = make_float4(wy0 * wx0, wy0 * wx1, wy1 * wx0, wy1 * wx1);
            ib[tid] = ((int)fy + 3) * 69 + (int)fx + 3;
        }
        __syncthreads();

        // ---- S = Q^T K (3-term bf16 mma) ----
        float sacc[8][4] = {};
#pragma unroll
        for (int kc = 0; kc < 2; kc++) {
            int r0 = ((kc << 3) + tig) * 72;
            int r1 = ((kc << 3) + tig + 4) * 72;
#pragma unroll
            for (int j = 0; j < 8; j++) {
                int nn = (j << 3) + gid;
                unsigned bh2[2] = { khi[r0 + nn], khi[r1 + nn] };
                unsigned bl2[2] = { klo[r0 + nn], klo[r1 + nn] };
                mma_bf16(sacc[j], qh[kc], bh2);
                mma_bf16(sacc[j], qh[kc], bl2);
                mma_bf16(sacc[j], ql[kc], bh2);
            }
        }

        // ---- + rpe bias (precomputed weights; bf16 table) ----
#pragma unroll
        for (int j = 0; j < 8; j++) {
#pragma unroll
            for (int e = 0; e < 2; e++) {
                int nn = (j << 3) + (tig << 1) + e;
                float4 w = w4[nn];
                int idxb = ib[nn];
                int ia = idxb + moff0;
                float t00 = __uint_as_float((unsigned)tbs[ia] << 16);
                float t01 = __uint_as_float((unsigned)tbs[ia + 1] << 16);
                float t10 = __uint_as_float((unsigned)tbs[ia + 69] << 16);
                float t11 = __uint_as_float((unsigned)tbs[ia + 70] << 16);
                sacc[j][e] += w.x * t00 + w.y * t01 + w.z * t10 + w.w * t11;
                int ic = idxb + moff1;
                t00 = __uint_as_float((unsigned)tbs[ic] << 16);
                t01 = __uint_as_float((unsigned)tbs[ic + 1] << 16);
                t10 = __uint_as_float((unsigned)tbs[ic + 69] << 16);
                t11 = __uint_as_float((unsigned)tbs[ic + 70] << 16);
                sacc[j][2 + e] += w.x * t00 + w.y * t01 + w.z * t10 + w.w * t11;
            }
        }

        // ---- online softmax (rows mA, mA+8; quad shuffles) ----
        float tm0 = -1e30f, tm1 = -1e30f;
#pragma unroll
        for (int j = 0; j < 8; j++) {
            tm0 = fmaxf(tm0, fmaxf(sacc[j][0], sacc[j][1]));
            tm1 = fmaxf(tm1, fmaxf(sacc[j][2], sacc[j][3]));
        }
        tm0 = fmaxf(tm0, __shfl_xor_sync(0xffffffffu, tm0, 1));
        tm0 = fmaxf(tm0, __shfl_xor_sync(0xffffffffu, tm0, 2));
        tm1 = fmaxf(tm1, __shfl_xor_sync(0xffffffffu, tm1, 1));
        tm1 = fmaxf(tm1, __shfl_xor_sync(0xffffffffu, tm1, 2));
        float nm0 = fmaxf(runm0, tm0), nm1 = fmaxf(runm1, tm1);
        float corr0 = __expf(runm0 - nm0), corr1 = __expf(runm1 - nm1);
        runm0 = nm0; runm1 = nm1;
        float lsum0 = 0.f, lsum1 = 0.f;
        int pr0 = (wm + gid) * 36;
        int pr1 = (wm + gid + 8) * 36;
#pragma unroll
        for (int j = 0; j < 8; j++) {
            float p0 = __expf(sacc[j][0] - nm0);
            float p1 = __expf(sacc[j][1] - nm0);
            float p2 = __expf(sacc[j][2] - nm1);
            float p3 = __expf(sacc[j][3] - nm1);
            lsum0 += p0 + p1; lsum1 += p2 + p3;
            unsigned h, l;
            int np = (j << 2) + tig;
            bsplit2(p0, p1, h, l);
            phi[pr0 + np] = h; plo[pr0 + np] = l;
            bsplit2(p2, p3, h, l);
            phi[pr1 + np] = h; plo[pr1 + np] = l;
        }
        rsum0 = rsum0 * corr0 + lsum0;
        rsum1 = rsum1 * corr1 + lsum1;
#pragma unroll
        for (int ct = 0; ct < 4; ct++) {
            oacc[ct][0] *= corr0; oacc[ct][1] *= corr0;
            oacc[ct][2] *= corr1; oacc[ct][3] *= corr1;
        }
        __syncwarp();   // P rows are warp-private

        // ---- O += P V (3-term bf16 mma) ----
#pragma unroll
        for (int ch = 0; ch < 4; ch++) {
            unsigned ah[4], al[4];
            int npA = (ch << 3) + tig;
            ah[0] = phi[pr0 + npA];     al[0] = plo[pr0 + npA];
            ah[1] = phi[pr1 + npA];     al[1] = plo[pr1 + npA];
            ah[2] = phi[pr0 + npA + 4]; al[2] = plo[pr0 + npA + 4];
            ah[3] = phi[pr1 + npA + 4]; al[3] = plo[pr1 + npA + 4];
#pragma unroll
            for (int ct = 0; ct < 4; ct++) {
                int cc = (ct << 3) + gid;
                unsigned bh2[2] = { vhi[npA * 40 + cc], vhi[(npA + 4) * 40 + cc] };
                unsigned bl2[2] = { vlo[npA * 40 + cc], vlo[(npA + 4) * 40 + cc] };
                mma_bf16(oacc[ct], ah, bh2);
                mma_bf16(oacc[ct], ah, bl2);
                mma_bf16(oacc[ct], al, bh2);
            }
        }
    }

    rsum0 += __shfl_xor_sync(0xffffffffu, rsum0, 1);
    rsum0 += __shfl_xor_sync(0xffffffffu, rsum0, 2);
    rsum1 += __shfl_xor_sync(0xffffffffu, rsum1, 1);
    rsum1 += __shfl_xor_sync(0xffffffffu, rsum1, 2);
    float inv0 = 1.f / rsum0, inv1 = 1.f / rsum1;

    // normalize + transpose via smem (reuse PHI/PLO region as float [64][68])
    float* obuf = (float*)(sm_ + FL_PHI);
    __syncthreads();
#pragma unroll
    for (int ct = 0; ct < 4; ct++) {
        int cc = (ct << 3) + (tig << 1);
        *(float2*)&obuf[(wm + gid) * 68 + cc] =
            make_float2(oacc[ct][0] * inv0, oacc[ct][1] * inv0);
        *(float2*)&obuf[(wm + gid + 8) * 68 + cc] =
            make_float2(oacc[ct][2] * inv1, oacc[ct][3] * inv1);
    }
    __syncthreads();
    float* ob = g_o + (size_t)(b * C_ + hd * HC_) * N_;
    for (int i = tid; i < 2048; i += 128) {
        int c = i >> 6, m = i & 63;
        ob[(size_t)c * N_ + m0 + m] = obuf[m * 68 + c];
    }
}

// ============================================================
extern "C" void kernel_launch(void* const* d_in, const int* in_sizes, int n_in,
                              void* d_out, int out_size) {
    const float* q_feat = (const float*)d_in[0];
    const float* kv_feat = (const float*)d_in[1];
    const float* Wq = (const float*)d_in[2];
    const float* bq = (const float*)d_in[3];
    const float* Wk = (const float*)d_in[4];
    const float* bk = (const float*)d_in[5];
    const float* Wv = (const float*)d_in[6];
    const float* bv = (const float*)d_in[7];
    const float* Wo = (const float*)d_in[8];
    const float* bo = (const float*)d_in[9];
    const float* dw_w = (const float*)d_in[10];
    const float* dw_b = (const float*)d_in[11];
    const float* ln_w = (const float*)d_in[12];
    const float* ln_b = (const float*)d_in[13];
    const float* pw_w = (const float*)d_in[14];
    const float* rpe  = (const float*)d_in[15];
    float* out = (float*)d_out;

    float *gq, *gxs, *gk, *gv, *go;
    cudaGetSymbolAddress((void**)&gq,  g_q);
    cudaGetSymbolAddress((void**)&gxs, g_xs);
    cudaGetSymbolAddress((void**)&gk,  g_k);
    cudaGetSymbolAddress((void**)&gv,  g_v);
    cudaGetSymbolAddress((void**)&go,  g_o);

    static int smem_set = 0;
    if (!smem_set) {
        cudaFuncSetAttribute(flash_kernel,
                             cudaFuncAttributeMaxDynamicSharedMemorySize, FL_SMEM);
        smem_set = 1;
    }

    dim3 gemm_grid(N_ / 64, C_ / 64, B_);
    dim3 kv_grid(N_ / 64, C_ / 64, B_ * 2);

    gemm_proj<<<gemm_grid, 128>>>(Wq, bq, q_feat, gq);
    offset_kernel<<<(BG_ * N_ * 4) / 256, 256>>>(dw_w, dw_b, ln_w, ln_b, pw_w);
    sample_kernel<<<BG_ * N_, GC_>>>(kv_feat);
    gemm_kv<<<kv_grid, 128>>>(Wk, bk, Wv, bv, gxs, gk, gv);
    flash_kernel<<<dim3(N_ / 64, B_ * NH_), 128, FL_SMEM>>>(rpe);
    gemm_proj<<<gemm_grid, 128>>>(Wo, bo, go, out);
}

// round 16
// speedup vs baseline: 1.6320x; 1.1862x over previous
#include <cuda_runtime.h>
#include <math.h>

#define B_   4
#define C_   256
#define H_   32
#define W_   32
#define N_   1024
#define NH_  8
#define HC_  32
#define NG_  4
#define GC_  64
#define BG_  16
#define SCALE_ 0.17677669529663687f   /* 32^-0.5 */
#define EPS_  1e-5f

// ---- scratch (device globals; no allocations allowed) ----
__device__ float g_q  [B_*C_*N_];
__device__ float g_pos[BG_*N_*2];
__device__ float g_xs [B_*C_*N_];
__device__ float g_k  [B_*C_*N_];
__device__ float g_v  [B_*C_*N_];
__device__ float g_o  [B_*C_*N_];

// ---- bf16 split-pack helpers ----
__device__ __forceinline__ unsigned bpack(float e0, float e1) {
    unsigned r; asm("cvt.rn.bf16x2.f32 %0, %1, %2;" : "=r"(r) : "f"(e1), "f"(e0));
    return r;
}
__device__ __forceinline__ void bsplit2(float x0, float x1, unsigned& hi, unsigned& lo) {
    unsigned h = bpack(x0, x1);
    float h0 = __uint_as_float(h << 16);
    float h1 = __uint_as_float(h & 0xffff0000u);
    hi = h;
    lo = bpack(x0 - h0, x1 - h1);
}
__device__ __forceinline__ void mma_bf16(float* d, const unsigned* a, const unsigned* b) {
    asm("mma.sync.aligned.m16n8k16.row.col.f32.bf16.bf16.f32 "
        "{%0,%1,%2,%3}, {%4,%5,%6,%7}, {%8,%9}, {%0,%1,%2,%3};"
        : "+f"(d[0]), "+f"(d[1]), "+f"(d[2]), "+f"(d[3])
        : "r"(a[0]), "r"(a[1]), "r"(a[2]), "r"(a[3]), "r"(b[0]), "r"(b[1]));
}

// ============================================================
// Projection GEMM, 3-term bf16 mma, register double-buffered.
// ============================================================
__device__ __forceinline__ void gemm_tile_bf16(
        const float* __restrict__ Wt, const float* __restrict__ bias,
        const float* __restrict__ Xb, float* __restrict__ Yb,
        int p0, int o0,
        unsigned (*Wh)[72], unsigned (*Wl)[72],
        unsigned (*Xh)[72], unsigned (*Xl)[72]) {
    int tid = threadIdx.x;
    int lane = tid & 31, wid = tid >> 5;
    int gid = lane >> 2, tig = lane & 3;
    int wm0 = (wid >> 1) << 5;
    int wn0 = (wid & 1) << 5;

    int o  = tid >> 1, kq = (tid & 1) << 3, kp0 = (tid & 1) << 2;
    int kp = tid >> 4, p4 = (tid & 15) << 2;
    const float* wp = &Wt[(size_t)(o0 + o) * C_ + kq];
    const float* xpa = &Xb[(size_t)(2 * kp) * N_ + p0 + p4];
    const float* xpb = &Xb[(size_t)(2 * kp + 1) * N_ + p0 + p4];

    float acc[2][4][4] = {};
    float4 wa = *(const float4*)wp;
    float4 wb = *(const float4*)(wp + 4);
    float4 xa = *(const float4*)xpa;
    float4 xb = *(const float4*)xpb;

    for (int kt = 0; kt < C_; kt += 16) {
        bsplit2(wa.x, wa.y, Wh[kp0 + 0][o], Wl[kp0 + 0][o]);
        bsplit2(wa.z, wa.w, Wh[kp0 + 1][o], Wl[kp0 + 1][o]);
        bsplit2(wb.x, wb.y, Wh[kp0 + 2][o], Wl[kp0 + 2][o]);
        bsplit2(wb.z, wb.w, Wh[kp0 + 3][o], Wl[kp0 + 3][o]);
        {
            unsigned h0, l0, h1, l1, h2, l2, h3, l3;
            bsplit2(xa.x, xb.x, h0, l0);
            bsplit2(xa.y, xb.y, h1, l1);
            bsplit2(xa.z, xb.z, h2, l2);
            bsplit2(xa.w, xb.w, h3, l3);
            *(uint4*)&Xh[kp][p4] = make_uint4(h0, h1, h2, h3);
            *(uint4*)&Xl[kp][p4] = make_uint4(l0, l1, l2, l3);
        }
        __syncthreads();
        int nk = kt + 16;
        if (nk < C_) {
            wa = *(const float4*)(wp + nk);
            wb = *(const float4*)(wp + nk + 4);
            xa = *(const float4*)(xpa + (size_t)nk * N_);
            xb = *(const float4*)(xpb + (size_t)nk * N_);
        }

        unsigned ah[2][4], al[2][4], bh[4][2], bl[4][2];
#pragma unroll
        for (int mi = 0; mi < 2; mi++) {
            int r = wm0 + (mi << 4) + gid;
            ah[mi][0] = Wh[tig][r];     al[mi][0] = Wl[tig][r];
            ah[mi][1] = Wh[tig][r + 8]; al[mi][1] = Wl[tig][r + 8];
            ah[mi][2] = Wh[tig + 4][r];     al[mi][2] = Wl[tig + 4][r];
            ah[mi][3] = Wh[tig + 4][r + 8]; al[mi][3] = Wl[tig + 4][r + 8];
        }
#pragma unroll
        for (int ni = 0; ni < 4; ni++) {
            int cc = wn0 + (ni << 3) + gid;
            bh[ni][0] = Xh[tig][cc];     bl[ni][0] = Xl[tig][cc];
            bh[ni][1] = Xh[tig + 4][cc]; bl[ni][1] = Xl[tig + 4][cc];
        }
#pragma unroll
        for (int mi = 0; mi < 2; mi++)
#pragma unroll
            for (int ni = 0; ni < 4; ni++) {
                mma_bf16(acc[mi][ni], ah[mi], bh[ni]);
                mma_bf16(acc[mi][ni], ah[mi], bl[ni]);
                mma_bf16(acc[mi][ni], al[mi], bh[ni]);
            }
        __syncthreads();
    }

#pragma unroll
    for (int mi = 0; mi < 2; mi++) {
        int r = wm0 + (mi << 4) + gid;
        float bs0 = bias[o0 + r], bs1 = bias[o0 + r + 8];
#pragma unroll
        for (int ni = 0; ni < 4; ni++) {
            int cb = p0 + wn0 + (ni << 3) + (tig << 1);
            float* y0 = &Yb[(size_t)(o0 + r) * N_ + cb];
            float* y1 = &Yb[(size_t)(o0 + r + 8) * N_ + cb];
            *(float2*)y0 = make_float2(acc[mi][ni][0] + bs0, acc[mi][ni][1] + bs0);
            *(float2*)y1 = make_float2(acc[mi][ni][2] + bs1, acc[mi][ni][3] + bs1);
        }
    }
}

__global__ __launch_bounds__(128) void gemm_proj(
        const float* __restrict__ Wt, const float* __restrict__ bias,
        const float* __restrict__ X, float* __restrict__ Y) {
    __shared__ unsigned Wh[8][72], Wl[8][72], Xh[8][72], Xl[8][72];
    int b = blockIdx.z;
    gemm_tile_bf16(Wt, bias, X + (size_t)b * C_ * N_, Y + (size_t)b * C_ * N_,
                   blockIdx.x << 6, blockIdx.y << 6, Wh, Wl, Xh, Xl);
}

__global__ __launch_bounds__(128) void gemm_kv(
        const float* __restrict__ Wk, const float* __restrict__ bk,
        const float* __restrict__ Wv, const float* __restrict__ bv,
        const float* __restrict__ X, float* __restrict__ Yk, float* __restrict__ Yv) {
    __shared__ unsigned Wh[8][72], Wl[8][72], Xh[8][72], Xl[8][72];
    int z = blockIdx.z;
    int b = z >> 1, sel = z & 1;
    gemm_tile_bf16(sel ? Wv : Wk, sel ? bv : bk,
                   X + (size_t)b * C_ * N_, (sel ? Yv : Yk) + (size_t)b * C_ * N_,
                   blockIdx.x << 6, blockIdx.y << 6, Wh, Wl, Xh, Xl);
}

// ============================================================
// Offset network + deformable sampling, fused.
// 4 lanes per pixel: offset stats via quad shuffles, then each
// lane bilinearly samples its 16 kv channels.
// ============================================================
__global__ __launch_bounds__(256) void offset_sample_kernel(
        const float* __restrict__ dw_w, const float* __restrict__ dw_b,
        const float* __restrict__ ln_w, const float* __restrict__ ln_b,
        const float* __restrict__ pw_w, const float* __restrict__ kv) {
    int t = blockIdx.x * blockDim.x + threadIdx.x;
    int pix = t >> 2, q = t & 3;
    int bg = pix >> 10, p = pix & (N_ - 1);
    int h = p >> 5, w = p & 31;
    int b = bg >> 2, g = bg & 3;
    const float* qbase = g_q + (size_t)b * C_ * N_ + (size_t)g * GC_ * N_
                       + (size_t)q * 16 * N_;

    float x[16];
    float s1 = 0.f;
#pragma unroll
    for (int j = 0; j < 16; j++) {
        int c = q * 16 + j;
        const float* qc = qbase + j * N_;
        float tt = dw_b[c];
#pragma unroll
        for (int dy = 0; dy < 3; dy++) {
            int hh = h + dy - 1;
            if (hh < 0 || hh >= H_) continue;
#pragma unroll
            for (int dx = 0; dx < 3; dx++) {
                int ww = w + dx - 1;
                if (ww < 0 || ww >= W_) continue;
                tt += dw_w[c * 9 + dy * 3 + dx] * qc[hh * W_ + ww];
            }
        }
        x[j] = tt; s1 += tt;
    }
    s1 += __shfl_xor_sync(0xffffffffu, s1, 1);
    s1 += __shfl_xor_sync(0xffffffffu, s1, 2);
    float mu = s1 * (1.f / GC_);
    float s2 = 0.f;
#pragma unroll
    for (int j = 0; j < 16; j++) { float d = x[j] - mu; s2 += d * d; }
    s2 += __shfl_xor_sync(0xffffffffu, s2, 1);
    s2 += __shfl_xor_sync(0xffffffffu, s2, 2);
    float rinv = rsqrtf(s2 * (1.f / GC_) + EPS_);
    float off0 = 0.f, off1 = 0.f;
#pragma unroll
    for (int j = 0; j < 16; j++) {
        int c = q * 16 + j;
        float xn  = (x[j] - mu) * rinv * ln_w[c] + ln_b[c];
        float gel = 0.5f * xn * (1.f + erff(xn * 0.7071067811865476f));
        off0 += pw_w[c] * gel;
        off1 += pw_w[GC_ + c] * gel;
    }
    off0 += __shfl_xor_sync(0xffffffffu, off0, 1);
    off0 += __shfl_xor_sync(0xffffffffu, off0, 2);
    off1 += __shfl_xor_sync(0xffffffffu, off1, 1);
    off1 += __shfl_xor_sync(0xffffffffu, off1, 2);
    const float rng = 4.0f / 31.0f;
    float py = tanhf(off0) * rng + ((0.5f + (float)h) / 31.f) * 2.f - 1.f;
    float px = tanhf(off1) * rng + ((0.5f + (float)w) / 31.f) * 2.f - 1.f;
    if (q == 0) {
        g_pos[pix * 2 + 0] = py;
        g_pos[pix * 2 + 1] = px;
    }

    // ---- deformable bilinear sampling (16 channels per lane) ----
    float ix = (px + 1.f) * 15.5f;
    float iy = (py + 1.f) * 15.5f;
    float x0f = floorf(ix), y0f = floorf(iy);
    float wx1 = ix - x0f, wx0 = 1.f - wx1;
    float wy1 = iy - y0f, wy0 = 1.f - wy1;
    int x0 = (int)x0f, y0 = (int)y0f;
    bool yv0 = (unsigned)y0 < (unsigned)H_, yv1 = (unsigned)(y0 + 1) < (unsigned)H_;
    bool xv0 = (unsigned)x0 < (unsigned)W_, xv1 = (unsigned)(x0 + 1) < (unsigned)W_;
    float w00 = (yv0 && xv0) ? wy0 * wx0 : 0.f;
    float w01 = (yv0 && xv1) ? wy0 * wx1 : 0.f;
    float w10 = (yv1 && xv0) ? wy1 * wx0 : 0.f;
    float w11 = (yv1 && xv1) ? wy1 * wx1 : 0.f;
    int xc0 = min(max(x0, 0), W_ - 1), xc1 = min(max(x0 + 1, 0), W_ - 1);
    int yc0 = min(max(y0, 0), H_ - 1), yc1 = min(max(y0 + 1, 0), H_ - 1);
    int i00 = yc0 * W_ + xc0, i01 = yc0 * W_ + xc1;
    int i10 = yc1 * W_ + xc0, i11 = yc1 * W_ + xc1;
    const float* src = kv + ((size_t)b * C_ + g * GC_ + q * 16) * N_;
    float* dst = g_xs + ((size_t)b * C_ + g * GC_ + q * 16) * N_ + p;
#pragma unroll
    for (int j = 0; j < 16; j++) {
        const float* s = src + (size_t)j * N_;
        dst[(size_t)j * N_] = w00 * s[i00] + w01 * s[i01] + w10 * s[i10] + w11 * s[i11];
    }
}

// ============================================================
// Fused flash attention, 3-term bf16 mma.
// P kept entirely in registers (lane-local producer/consumer map).
// fp32 zero-padded RPE table; per-n bias weights precomputed.
// ============================================================
#define FL_KHI 0                 /* [16][72] u32 = 4608 */
#define FL_KLO 4608
#define FL_VHI 9216              /* [32][40] u32 = 5120 */
#define FL_VLO 14336
#define FL_TB  19456             /* float[69*69] = 19044 -> 19072 */
#define FL_W4  38528             /* 64 * float4 */
#define FL_IB  39552             /* 64 * int */
#define FL_SMEM 39808

__global__ __launch_bounds__(128) void flash_kernel(const float* __restrict__ rpe) {
    extern __shared__ char sm_[];
    unsigned* khi = (unsigned*)(sm_ + FL_KHI);
    unsigned* klo = (unsigned*)(sm_ + FL_KLO);
    unsigned* vhi = (unsigned*)(sm_ + FL_VHI);
    unsigned* vlo = (unsigned*)(sm_ + FL_VLO);
    float*    tb  = (float*)(sm_ + FL_TB);
    float4*   w4  = (float4*)(sm_ + FL_W4);
    int*      ib  = (int*)(sm_ + FL_IB);

    int tid = threadIdx.x;
    int lane = tid & 31, wid = tid >> 5;
    int gid = lane >> 2, tig = lane & 3;
    int wm = wid << 4;
    int bh = blockIdx.y, b = bh >> 3, hd = bh & 7;
    int m0 = blockIdx.x << 6;

    const float* qb = g_q + (size_t)(b * C_ + hd * HC_) * N_;
    const float* kb = g_k + (size_t)(b * C_ + hd * HC_) * N_;
    const float* vb = g_v + (size_t)(b * C_ + hd * HC_) * N_;
    const float* posb = g_pos + (size_t)(b * NG_ + (hd >> 1)) * N_ * 2;
    const float* tsrc = rpe + hd * 3969;

    for (int i = tid; i < 69 * 69; i += 128) tb[i] = 0.f;
    __syncthreads();
    for (int i = tid; i < 3969; i += 128) {
        int y = i / 63, x = i - y * 63;
        tb[(y + 3) * 69 + x + 3] = tsrc[i];
    }

    int mA = m0 + wm + gid;
    unsigned qh[2][4], ql[2][4];
#pragma unroll
    for (int kc = 0; kc < 2; kc++) {
        int cA = (kc << 4) + (tig << 1);
        int cB = cA + 8;
        float a00 = qb[(size_t)cA * N_ + mA] * SCALE_;
        float a01 = qb[(size_t)(cA + 1) * N_ + mA] * SCALE_;
        float a10 = qb[(size_t)cA * N_ + mA + 8] * SCALE_;
        float a11 = qb[(size_t)(cA + 1) * N_ + mA + 8] * SCALE_;
        float a20 = qb[(size_t)cB * N_ + mA] * SCALE_;
        float a21 = qb[(size_t)(cB + 1) * N_ + mA] * SCALE_;
        float a30 = qb[(size_t)cB * N_ + mA + 8] * SCALE_;
        float a31 = qb[(size_t)(cB + 1) * N_ + mA + 8] * SCALE_;
        bsplit2(a00, a01, qh[kc][0], ql[kc][0]);
        bsplit2(a10, a11, qh[kc][1], ql[kc][1]);
        bsplit2(a20, a21, qh[kc][2], ql[kc][2]);
        bsplit2(a30, a31, qh[kc][3], ql[kc][3]);
    }

    int moff0 = (mA >> 5) * 69 + (mA & 31);
    int moff1 = ((mA + 8) >> 5) * 69 + ((mA + 8) & 31);

    float runm0 = -1e30f, runm1 = -1e30f;
    float rsum0 = 0.f, rsum1 = 0.f;
    float oacc[4][4] = {};

    for (int nt = 0; nt < 16; nt++) {
        int n0 = nt << 6;
        __syncthreads();

        // stage K: khi/klo[kp][n], kp = c-pair
        for (int i = tid; i < 256; i += 128) {
            int kp = i >> 4, n4 = (i & 15) << 2;
            float4 ka = *(const float4*)&kb[(size_t)(2 * kp) * N_ + n0 + n4];
            float4 kc = *(const float4*)&kb[(size_t)(2 * kp + 1) * N_ + n0 + n4];
            unsigned h0, l0, h1, l1, h2, l2, h3, l3;
            bsplit2(ka.x, kc.x, h0, l0);
            bsplit2(ka.y, kc.y, h1, l1);
            bsplit2(ka.z, kc.z, h2, l2);
            bsplit2(ka.w, kc.w, h3, l3);
            *(uint4*)&khi[kp * 72 + n4] = make_uint4(h0, h1, h2, h3);
            *(uint4*)&klo[kp * 72 + n4] = make_uint4(l0, l1, l2, l3);
        }
        // stage V transposed: vhi/vlo[np][c], np = n-pair
        for (int i = tid; i < 512; i += 128) {
            int c = i >> 4, n4 = (i & 15) << 2;
            float4 vv = *(const float4*)&vb[(size_t)c * N_ + n0 + n4];
            unsigned h, l;
            int np = n4 >> 1;
            bsplit2(vv.x, vv.y, h, l);
            vhi[np * 40 + c] = h; vlo[np * 40 + c] = l;
            bsplit2(vv.z, vv.w, h, l);
            vhi[(np + 1) * 40 + c] = h; vlo[(np + 1) * 40 + c] = l;
        }
        if (tid < 64) {
            float biy = 15.5f - 15.5f * posb[(n0 + tid) * 2 + 0];
            float bix = 15.5f - 15.5f * posb[(n0 + tid) * 2 + 1];
            float fy = floorf(biy), fx = floorf(bix);
            float wy1 = biy - fy, wx1 = bix - fx;
            float wy0 = 1.f - wy1, wx0 = 1.f - wx1;
            w4[tid] = make_float4(wy0 * wx0, wy0 * wx1, wy1 * wx0, wy1 * wx1);
            ib[tid] = ((int)fy + 3) * 69 + (int)fx + 3;
        }
        __syncthreads();

        // ---- S = Q^T K ----
        float sacc[8][4] = {};
#pragma unroll
        for (int kc = 0; kc < 2; kc++) {
            int r0 = ((kc << 3) + tig) * 72;
            int r1 = ((kc << 3) + tig + 4) * 72;
#pragma unroll
            for (int j = 0; j < 8; j++) {
                int nn = (j << 3) + gid;
                unsigned bh2[2] = { khi[r0 + nn], khi[r1 + nn] };
                unsigned bl2[2] = { klo[r0 + nn], klo[r1 + nn] };
                mma_bf16(sacc[j], qh[kc], bh2);
                mma_bf16(sacc[j], qh[kc], bl2);
                mma_bf16(sacc[j], ql[kc], bh2);
            }
        }

        // ---- + rpe bias ----
#pragma unroll
        for (int j = 0; j < 8; j++) {
#pragma unroll
            for (int e = 0; e < 2; e++) {
                int nn = (j << 3) + (tig << 1) + e;
                float4 w = w4[nn];
                int idxb = ib[nn];
                int ia = idxb + moff0;
                sacc[j][e] += w.x * tb[ia] + w.y * tb[ia + 1]
                            + w.z * tb[ia + 69] + w.w * tb[ia + 70];
                int ic = idxb + moff1;
                sacc[j][2 + e] += w.x * tb[ic] + w.y * tb[ic + 1]
                                + w.z * tb[ic + 69] + w.w * tb[ic + 70];
            }
        }

        // ---- online softmax; P packed into registers (lane-local) ----
        float tm0 = -1e30f, tm1 = -1e30f;
#pragma unroll
        for (int j = 0; j < 8; j++) {
            tm0 = fmaxf(tm0, fmaxf(sacc[j][0], sacc[j][1]));
            tm1 = fmaxf(tm1, fmaxf(sacc[j][2], sacc[j][3]));
        }
        tm0 = fmaxf(tm0, __shfl_xor_sync(0xffffffffu, tm0, 1));
        tm0 = fmaxf(tm0, __shfl_xor_sync(0xffffffffu, tm0, 2));
        tm1 = fmaxf(tm1, __shfl_xor_sync(0xffffffffu, tm1, 1));
        tm1 = fmaxf(tm1, __shfl_xor_sync(0xffffffffu, tm1, 2));
        float nm0 = fmaxf(runm0, tm0), nm1 = fmaxf(runm1, tm1);
        float corr0 = __expf(runm0 - nm0), corr1 = __expf(runm1 - nm1);
        runm0 = nm0; runm1 = nm1;
        float lsum0 = 0.f, lsum1 = 0.f;
        unsigned pAh[8], pAl[8], pBh[8], pBl[8];
#pragma unroll
        for (int j = 0; j < 8; j++) {
            float p0 = __expf(sacc[j][0] - nm0);
            float p1 = __expf(sacc[j][1] - nm0);
            float p2 = __expf(sacc[j][2] - nm1);
            float p3 = __expf(sacc[j][3] - nm1);
            lsum0 += p0 + p1; lsum1 += p2 + p3;
            bsplit2(p0, p1, pAh[j], pAl[j]);
            bsplit2(p2, p3, pBh[j], pBl[j]);
        }
        rsum0 = rsum0 * corr0 + lsum0;
        rsum1 = rsum1 * corr1 + lsum1;
#pragma unroll
        for (int ct = 0; ct < 4; ct++) {
            oacc[ct][0] *= corr0; oacc[ct][1] *= corr0;
            oacc[ct][2] *= corr1; oacc[ct][3] *= corr1;
        }

        // ---- O += P V (A-fragments straight from registers) ----
#pragma unroll
        for (int ch = 0; ch < 4; ch++) {
            unsigned ah[4] = { pAh[2 * ch], pBh[2 * ch], pAh[2 * ch + 1], pBh[2 * ch + 1] };
            unsigned al[4] = { pAl[2 * ch], pBl[2 * ch], pAl[2 * ch + 1], pBl[2 * ch + 1] };
            int npA = (ch << 3) + tig;
#pragma unroll
            for (int ct = 0; ct < 4; ct++) {
                int cc = (ct << 3) + gid;
                unsigned bh2[2] = { vhi[npA * 40 + cc], vhi[(npA + 4) * 40 + cc] };
                unsigned bl2[2] = { vlo[npA * 40 + cc], vlo[(npA + 4) * 40 + cc] };
                mma_bf16(oacc[ct], ah, bh2);
                mma_bf16(oacc[ct], ah, bl2);
                mma_bf16(oacc[ct], al, bh2);
            }
        }
    }

    rsum0 += __shfl_xor_sync(0xffffffffu, rsum0, 1);
    rsum0 += __shfl_xor_sync(0xffffffffu, rsum0, 2);
    rsum1 += __shfl_xor_sync(0xffffffffu, rsum1, 1);
    rsum1 += __shfl_xor_sync(0xffffffffu, rsum1, 2);
    float inv0 = 1.f / rsum0, inv1 = 1.f / rsum1;

    // normalize + transpose via smem (reuse K/V region as float [64][68])
    float* obuf = (float*)sm_;
    __syncthreads();
#pragma unroll
    for (int ct = 0; ct < 4; ct++) {
        int cc = (ct << 3) + (tig << 1);
        *(float2*)&obuf[(wm + gid) * 68 + cc] =
            make_float2(oacc[ct][0] * inv0, oacc[ct][1] * inv0);
        *(float2*)&obuf[(wm + gid + 8) * 68 + cc] =
            make_float2(oacc[ct][2] * inv1, oacc[ct][3] * inv1);
    }
    __syncthreads();
    float* ob = g_o + (size_t)(b * C_ + hd * HC_) * N_;
    for (int i = tid; i < 2048; i += 128) {
        int c = i >> 6, m = i & 63;
        ob[(size_t)c * N_ + m0 + m] = obuf[m * 68 + c];
    }
}

// ============================================================
extern "C" void kernel_launch(void* const* d_in, const int* in_sizes, int n_in,
                              void* d_out, int out_size) {
    const float* q_feat = (const float*)d_in[0];
    const float* kv_feat = (const float*)d_in[1];
    const float* Wq = (const float*)d_in[2];
    const float* bq = (const float*)d_in[3];
    const float* Wk = (const float*)d_in[4];
    const float* bk = (const float*)d_in[5];
    const float* Wv = (const float*)d_in[6];
    const float* bv = (const float*)d_in[7];
    const float* Wo = (const float*)d_in[8];
    const float* bo = (const float*)d_in[9];
    const float* dw_w = (const float*)d_in[10];
    const float* dw_b = (const float*)d_in[11];
    const float* ln_w = (const float*)d_in[12];
    const float* ln_b = (const float*)d_in[13];
    const float* pw_w = (const float*)d_in[14];
    const float* rpe  = (const float*)d_in[15];
    float* out = (float*)d_out;

    float *gq, *gxs, *gk, *gv, *go;
    cudaGetSymbolAddress((void**)&gq,  g_q);
    cudaGetSymbolAddress((void**)&gxs, g_xs);
    cudaGetSymbolAddress((void**)&gk,  g_k);
    cudaGetSymbolAddress((void**)&gv,  g_v);
    cudaGetSymbolAddress((void**)&go,  g_o);

    static int smem_set = 0;
    if (!smem_set) {
        cudaFuncSetAttribute(flash_kernel,
                             cudaFuncAttributeMaxDynamicSharedMemorySize, FL_SMEM);
        smem_set = 1;
    }

    dim3 gemm_grid(N_ / 64, C_ / 64, B_);
    dim3 kv_grid(N_ / 64, C_ / 64, B_ * 2);

    gemm_proj<<<gemm_grid, 128>>>(Wq, bq, q_feat, gq);
    offset_sample_kernel<<<(BG_ * N_ * 4) / 256, 256>>>(dw_w, dw_b, ln_w, ln_b, pw_w, kv_feat);
    gemm_kv<<<kv_grid, 128>>>(Wk, bk, Wv, bv, gxs, gk, gv);
    flash_kernel<<<dim3(N_ / 64, B_ * NH_), 128, FL_SMEM>>>(rpe);
    gemm_proj<<<gemm_grid, 128>>>(Wo, bo, go, out);
}

// round 17
// speedup vs baseline: 1.6861x; 1.0332x over previous
#include <cuda_runtime.h>
#include <math.h>

#define B_   4
#define C_   256
#define H_   32
#define W_   32
#define N_   1024
#define NH_  8
#define HC_  32
#define NG_  4
#define GC_  64
#define BG_  16
#define SCALE_ 0.17677669529663687f   /* 32^-0.5 */
#define EPS_  1e-5f

// ---- scratch (device globals; no allocations allowed) ----
__device__ float g_q  [B_*C_*N_];
__device__ float g_pos[BG_*N_*2];
__device__ float g_xs [B_*C_*N_];
__device__ float g_k  [B_*C_*N_];
__device__ float g_v  [B_*C_*N_];
__device__ float g_o  [B_*C_*N_];

// ---- bf16 split-pack helpers ----
__device__ __forceinline__ unsigned bpack(float e0, float e1) {
    unsigned r; asm("cvt.rn.bf16x2.f32 %0, %1, %2;" : "=r"(r) : "f"(e1), "f"(e0));
    return r;
}
__device__ __forceinline__ void bsplit2(float x0, float x1, unsigned& hi, unsigned& lo) {
    unsigned h = bpack(x0, x1);
    float h0 = __uint_as_float(h << 16);
    float h1 = __uint_as_float(h & 0xffff0000u);
    hi = h;
    lo = bpack(x0 - h0, x1 - h1);
}
__device__ __forceinline__ void mma_bf16(float* d, const unsigned* a, const unsigned* b) {
    asm("mma.sync.aligned.m16n8k16.row.col.f32.bf16.bf16.f32 "
        "{%0,%1,%2,%3}, {%4,%5,%6,%7}, {%8,%9}, {%0,%1,%2,%3};"
        : "+f"(d[0]), "+f"(d[1]), "+f"(d[2]), "+f"(d[3])
        : "r"(a[0]), "r"(a[1]), "r"(a[2]), "r"(a[3]), "r"(b[0]), "r"(b[1]));
}

// ============================================================
// Projection GEMM, 3-term bf16 mma, register double-buffered.
// (unchanged from R16 winner)
// ============================================================
__device__ __forceinline__ void gemm_tile_bf16(
        const float* __restrict__ Wt, const float* __restrict__ bias,
        const float* __restrict__ Xb, float* __restrict__ Yb,
        int p0, int o0,
        unsigned (*Wh)[72], unsigned (*Wl)[72],
        unsigned (*Xh)[72], unsigned (*Xl)[72]) {
    int tid = threadIdx.x;
    int lane = tid & 31, wid = tid >> 5;
    int gid = lane >> 2, tig = lane & 3;
    int wm0 = (wid >> 1) << 5;
    int wn0 = (wid & 1) << 5;

    int o  = tid >> 1, kq = (tid & 1) << 3, kp0 = (tid & 1) << 2;
    int kp = tid >> 4, p4 = (tid & 15) << 2;
    const float* wp = &Wt[(size_t)(o0 + o) * C_ + kq];
    const float* xpa = &Xb[(size_t)(2 * kp) * N_ + p0 + p4];
    const float* xpb = &Xb[(size_t)(2 * kp + 1) * N_ + p0 + p4];

    float acc[2][4][4] = {};
    float4 wa = *(const float4*)wp;
    float4 wb = *(const float4*)(wp + 4);
    float4 xa = *(const float4*)xpa;
    float4 xb = *(const float4*)xpb;

    for (int kt = 0; kt < C_; kt += 16) {
        bsplit2(wa.x, wa.y, Wh[kp0 + 0][o], Wl[kp0 + 0][o]);
        bsplit2(wa.z, wa.w, Wh[kp0 + 1][o], Wl[kp0 + 1][o]);
        bsplit2(wb.x, wb.y, Wh[kp0 + 2][o], Wl[kp0 + 2][o]);
        bsplit2(wb.z, wb.w, Wh[kp0 + 3][o], Wl[kp0 + 3][o]);
        {
            unsigned h0, l0, h1, l1, h2, l2, h3, l3;
            bsplit2(xa.x, xb.x, h0, l0);
            bsplit2(xa.y, xb.y, h1, l1);
            bsplit2(xa.z, xb.z, h2, l2);
            bsplit2(xa.w, xb.w, h3, l3);
            *(uint4*)&Xh[kp][p4] = make_uint4(h0, h1, h2, h3);
            *(uint4*)&Xl[kp][p4] = make_uint4(l0, l1, l2, l3);
        }
        __syncthreads();
        int nk = kt + 16;
        if (nk < C_) {
            wa = *(const float4*)(wp + nk);
            wb = *(const float4*)(wp + nk + 4);
            xa = *(const float4*)(xpa + (size_t)nk * N_);
            xb = *(const float4*)(xpb + (size_t)nk * N_);
        }

        unsigned ah[2][4], al[2][4], bh[4][2], bl[4][2];
#pragma unroll
        for (int mi = 0; mi < 2; mi++) {
            int r = wm0 + (mi << 4) + gid;
            ah[mi][0] = Wh[tig][r];     al[mi][0] = Wl[tig][r];
            ah[mi][1] = Wh[tig][r + 8]; al[mi][1] = Wl[tig][r + 8];
            ah[mi][2] = Wh[tig + 4][r];     al[mi][2] = Wl[tig + 4][r];
            ah[mi][3] = Wh[tig + 4][r + 8]; al[mi][3] = Wl[tig + 4][r + 8];
        }
#pragma unroll
        for (int ni = 0; ni < 4; ni++) {
            int cc = wn0 + (ni << 3) + gid;
            bh[ni][0] = Xh[tig][cc];     bl[ni][0] = Xl[tig][cc];
            bh[ni][1] = Xh[tig + 4][cc]; bl[ni][1] = Xl[tig + 4][cc];
        }
#pragma unroll
        for (int mi = 0; mi < 2; mi++)
#pragma unroll
            for (int ni = 0; ni < 4; ni++) {
                mma_bf16(acc[mi][ni], ah[mi], bh[ni]);
                mma_bf16(acc[mi][ni], ah[mi], bl[ni]);
                mma_bf16(acc[mi][ni], al[mi], bh[ni]);
            }
        __syncthreads();
    }

#pragma unroll
    for (int mi = 0; mi < 2; mi++) {
        int r = wm0 + (mi << 4) + gid;
        float bs0 = bias[o0 + r], bs1 = bias[o0 + r + 8];
#pragma unroll
        for (int ni = 0; ni < 4; ni++) {
            int cb = p0 + wn0 + (ni << 3) + (tig << 1);
            float* y0 = &Yb[(size_t)(o0 + r) * N_ + cb];
            float* y1 = &Yb[(size_t)(o0 + r + 8) * N_ + cb];
            *(float2*)y0 = make_float2(acc[mi][ni][0] + bs0, acc[mi][ni][1] + bs0);
            *(float2*)y1 = make_float2(acc[mi][ni][2] + bs1, acc[mi][ni][3] + bs1);
        }
    }
}

__global__ __launch_bounds__(128) void gemm_proj(
        const float* __restrict__ Wt, const float* __restrict__ bias,
        const float* __restrict__ X, float* __restrict__ Y) {
    __shared__ unsigned Wh[8][72], Wl[8][72], Xh[8][72], Xl[8][72];
    int b = blockIdx.z;
    gemm_tile_bf16(Wt, bias, X + (size_t)b * C_ * N_, Y + (size_t)b * C_ * N_,
                   blockIdx.x << 6, blockIdx.y << 6, Wh, Wl, Xh, Xl);
}

__global__ __launch_bounds__(128) void gemm_kv(
        const float* __restrict__ Wk, const float* __restrict__ bk,
        const float* __restrict__ Wv, const float* __restrict__ bv,
        const float* __restrict__ X, float* __restrict__ Yk, float* __restrict__ Yv) {
    __shared__ unsigned Wh[8][72], Wl[8][72], Xh[8][72], Xl[8][72];
    int z = blockIdx.z;
    int b = z >> 1, sel = z & 1;
    gemm_tile_bf16(sel ? Wv : Wk, sel ? bv : bk,
                   X + (size_t)b * C_ * N_, (sel ? Yv : Yk) + (size_t)b * C_ * N_,
                   blockIdx.x << 6, blockIdx.y << 6, Wh, Wl, Xh, Xl);
}

// ============================================================
// Offset network + deformable sampling, fused. (unchanged)
// ============================================================
__global__ __launch_bounds__(256) void offset_sample_kernel(
        const float* __restrict__ dw_w, const float* __restrict__ dw_b,
        const float* __restrict__ ln_w, const float* __restrict__ ln_b,
        const float* __restrict__ pw_w, const float* __restrict__ kv) {
    int t = blockIdx.x * blockDim.x + threadIdx.x;
    int pix = t >> 2, q = t & 3;
    int bg = pix >> 10, p = pix & (N_ - 1);
    int h = p >> 5, w = p & 31;
    int b = bg >> 2, g = bg & 3;
    const float* qbase = g_q + (size_t)b * C_ * N_ + (size_t)g * GC_ * N_
                       + (size_t)q * 16 * N_;

    float x[16];
    float s1 = 0.f;
#pragma unroll
    for (int j = 0; j < 16; j++) {
        int c = q * 16 + j;
        const float* qc = qbase + j * N_;
        float tt = dw_b[c];
#pragma unroll
        for (int dy = 0; dy < 3; dy++) {
            int hh = h + dy - 1;
            if (hh < 0 || hh >= H_) continue;
#pragma unroll
            for (int dx = 0; dx < 3; dx++) {
                int ww = w + dx - 1;
                if (ww < 0 || ww >= W_) continue;
                tt += dw_w[c * 9 + dy * 3 + dx] * qc[hh * W_ + ww];
            }
        }
        x[j] = tt; s1 += tt;
    }
    s1 += __shfl_xor_sync(0xffffffffu, s1, 1);
    s1 += __shfl_xor_sync(0xffffffffu, s1, 2);
    float mu = s1 * (1.f / GC_);
    float s2 = 0.f;
#pragma unroll
    for (int j = 0; j < 16; j++) { float d = x[j] - mu; s2 += d * d; }
    s2 += __shfl_xor_sync(0xffffffffu, s2, 1);
    s2 += __shfl_xor_sync(0xffffffffu, s2, 2);
    float rinv = rsqrtf(s2 * (1.f / GC_) + EPS_);
    float off0 = 0.f, off1 = 0.f;
#pragma unroll
    for (int j = 0; j < 16; j++) {
        int c = q * 16 + j;
        float xn  = (x[j] - mu) * rinv * ln_w[c] + ln_b[c];
        float gel = 0.5f * xn * (1.f + erff(xn * 0.7071067811865476f));
        off0 += pw_w[c] * gel;
        off1 += pw_w[GC_ + c] * gel;
    }
    off0 += __shfl_xor_sync(0xffffffffu, off0, 1);
    off0 += __shfl_xor_sync(0xffffffffu, off0, 2);
    off1 += __shfl_xor_sync(0xffffffffu, off1, 1);
    off1 += __shfl_xor_sync(0xffffffffu, off1, 2);
    const float rng = 4.0f / 31.0f;
    float py = tanhf(off0) * rng + ((0.5f + (float)h) / 31.f) * 2.f - 1.f;
    float px = tanhf(off1) * rng + ((0.5f + (float)w) / 31.f) * 2.f - 1.f;
    if (q == 0) {
        g_pos[pix * 2 + 0] = py;
        g_pos[pix * 2 + 1] = px;
    }

    float ix = (px + 1.f) * 15.5f;
    float iy = (py + 1.f) * 15.5f;
    float x0f = floorf(ix), y0f = floorf(iy);
    float wx1 = ix - x0f, wx0 = 1.f - wx1;
    float wy1 = iy - y0f, wy0 = 1.f - wy1;
    int x0 = (int)x0f, y0 = (int)y0f;
    bool yv0 = (unsigned)y0 < (unsigned)H_, yv1 = (unsigned)(y0 + 1) < (unsigned)H_;
    bool xv0 = (unsigned)x0 < (unsigned)W_, xv1 = (unsigned)(x0 + 1) < (unsigned)W_;
    float w00 = (yv0 && xv0) ? wy0 * wx0 : 0.f;
    float w01 = (yv0 && xv1) ? wy0 * wx1 : 0.f;
    float w10 = (yv1 && xv0) ? wy1 * wx0 : 0.f;
    float w11 = (yv1 && xv1) ? wy1 * wx1 : 0.f;
    int xc0 = min(max(x0, 0), W_ - 1), xc1 = min(max(x0 + 1, 0), W_ - 1);
    int yc0 = min(max(y0, 0), H_ - 1), yc1 = min(max(y0 + 1, 0), H_ - 1);
    int i00 = yc0 * W_ + xc0, i01 = yc0 * W_ + xc1;
    int i10 = yc1 * W_ + xc0, i11 = yc1 * W_ + xc1;
    const float* src = kv + ((size_t)b * C_ + g * GC_ + q * 16) * N_;
    float* dst = g_xs + ((size_t)b * C_ + g * GC_ + q * 16) * N_ + p;
#pragma unroll
    for (int j = 0; j < 16; j++) {
        const float* s = src + (size_t)j * N_;
        dst[(size_t)j * N_] = w00 * s[i00] + w01 * s[i01] + w10 * s[i10] + w11 * s[i11];
    }
}

// ============================================================
// Fused flash attention, 3-term bf16 mma.
// K/V tiles stored as interleaved uint2(hi,lo) -> LDS.64 fragments.
// RPE table as overlapping bf16 pairs -> 1 LDS per 2 x-taps.
// P in registers (lane-local).
// ============================================================
#define FL_KHL 0                 /* uint2[16*68] = 8704 */
#define FL_VHL 8704              /* uint2[32*36] = 9216 */
#define FL_TBP 17920             /* u32[69*69] = 19044 -> 19072 */
#define FL_W4  36992             /* 64 * float4 */
#define FL_IB  38016             /* 64 * int */
#define FL_SMEM 38272

__global__ __launch_bounds__(128) void flash_kernel(const float* __restrict__ rpe) {
    extern __shared__ char sm_[];
    uint2*    khl = (uint2*)(sm_ + FL_KHL);      // [16 kp][68 n] (hi,lo)
    uint2*    vhl = (uint2*)(sm_ + FL_VHL);      // [32 np][36 c] (hi,lo)
    unsigned* tbp = (unsigned*)(sm_ + FL_TBP);   // [69][69] bf16 pairs (t[i],t[i+1])
    float4*   w4  = (float4*)(sm_ + FL_W4);
    int*      ib  = (int*)(sm_ + FL_IB);

    int tid = threadIdx.x;
    int lane = tid & 31, wid = tid >> 5;
    int gid = lane >> 2, tig = lane & 3;
    int wm = wid << 4;
    int bh = blockIdx.y, b = bh >> 3, hd = bh & 7;
    int m0 = blockIdx.x << 6;

    const float* qb = g_q + (size_t)(b * C_ + hd * HC_) * N_;
    const float* kb = g_k + (size_t)(b * C_ + hd * HC_) * N_;
    const float* vb = g_v + (size_t)(b * C_ + hd * HC_) * N_;
    const float* posb = g_pos + (size_t)(b * NG_ + (hd >> 1)) * N_ * 2;
    const float* tsrc = rpe + hd * 3969;

    // build padded pair table in one pass (guarded global reads)
    for (int i = tid; i < 69 * 69; i += 128) {
        int yy = i / 69, xx = i - yy * 69;
        int y = yy - 3, x0 = xx - 3;
        bool yv = (unsigned)y < 63u;
        float v0 = (yv && (unsigned)x0 < 63u) ? tsrc[y * 63 + x0] : 0.f;
        float v1 = (yv && (unsigned)(x0 + 1) < 63u) ? tsrc[y * 63 + x0 + 1] : 0.f;
        tbp[i] = bpack(v0, v1);
    }

    // Q fragments: 2 k16-chunks over c, packed bf16 pairs
    int mA = m0 + wm + gid;
    unsigned qh[2][4], ql[2][4];
#pragma unroll
    for (int kc = 0; kc < 2; kc++) {
        int cA = (kc << 4) + (tig << 1);
        int cB = cA + 8;
        float a00 = qb[(size_t)cA * N_ + mA] * SCALE_;
        float a01 = qb[(size_t)(cA + 1) * N_ + mA] * SCALE_;
        float a10 = qb[(size_t)cA * N_ + mA + 8] * SCALE_;
        float a11 = qb[(size_t)(cA + 1) * N_ + mA + 8] * SCALE_;
        float a20 = qb[(size_t)cB * N_ + mA] * SCALE_;
        float a21 = qb[(size_t)(cB + 1) * N_ + mA] * SCALE_;
        float a30 = qb[(size_t)cB * N_ + mA + 8] * SCALE_;
        float a31 = qb[(size_t)(cB + 1) * N_ + mA + 8] * SCALE_;
        bsplit2(a00, a01, qh[kc][0], ql[kc][0]);
        bsplit2(a10, a11, qh[kc][1], ql[kc][1]);
        bsplit2(a20, a21, qh[kc][2], ql[kc][2]);
        bsplit2(a30, a31, qh[kc][3], ql[kc][3]);
    }

    int moff0 = (mA >> 5) * 69 + (mA & 31);
    int moff1 = ((mA + 8) >> 5) * 69 + ((mA + 8) & 31);

    float runm0 = -1e30f, runm1 = -1e30f;
    float rsum0 = 0.f, rsum1 = 0.f;
    float oacc[4][4] = {};

    for (int nt = 0; nt < 16; nt++) {
        int n0 = nt << 6;
        __syncthreads();   // prior tile's reads done (iter 0: table build done)

        // stage K interleaved: khl[kp][n] = (hi, lo)
        for (int i = tid; i < 256; i += 128) {
            int kp = i >> 4, n4 = (i & 15) << 2;
            float4 ka = *(const float4*)&kb[(size_t)(2 * kp) * N_ + n0 + n4];
            float4 kc4 = *(const float4*)&kb[(size_t)(2 * kp + 1) * N_ + n0 + n4];
            unsigned h0, l0, h1, l1, h2, l2, h3, l3;
            bsplit2(ka.x, kc4.x, h0, l0);
            bsplit2(ka.y, kc4.y, h1, l1);
            bsplit2(ka.z, kc4.z, h2, l2);
            bsplit2(ka.w, kc4.w, h3, l3);
            *(uint4*)(khl + kp * 68 + n4)     = make_uint4(h0, l0, h1, l1);
            *(uint4*)(khl + kp * 68 + n4 + 2) = make_uint4(h2, l2, h3, l3);
        }
        // stage V interleaved transposed: vhl[np][c] = (hi, lo)
        for (int i = tid; i < 512; i += 128) {
            int c = i >> 4, n4 = (i & 15) << 2;
            float4 vv = *(const float4*)&vb[(size_t)c * N_ + n0 + n4];
            unsigned h, l;
            int np = n4 >> 1;
            bsplit2(vv.x, vv.y, h, l);
            vhl[np * 36 + c] = make_uint2(h, l);
            bsplit2(vv.z, vv.w, h, l);
            vhl[(np + 1) * 36 + c] = make_uint2(h, l);
        }
        if (tid < 64) {
            float biy = 15.5f - 15.5f * posb[(n0 + tid) * 2 + 0];
            float bix = 15.5f - 15.5f * posb[(n0 + tid) * 2 + 1];
            float fy = floorf(biy), fx = floorf(bix);
            float wy1 = biy - fy, wx1 = bix - fx;
            float wy0 = 1.f - wy1, wx0 = 1.f - wx1;
            w4[tid] = make_float4(wy0 * wx0, wy0 * wx1, wy1 * wx0, wy1 * wx1);
            ib[tid] = ((int)fy + 3) * 69 + (int)fx + 3;
        }
        __syncthreads();

        // ---- S = Q^T K (B-fragments via LDS.64) ----
        float sacc[8][4] = {};
#pragma unroll
        for (int kc = 0; kc < 2; kc++) {
            int r0 = ((kc << 3) + tig) * 68;
            int r1 = ((kc << 3) + tig + 4) * 68;
#pragma unroll
            for (int j = 0; j < 8; j++) {
                int nn = (j << 3) + gid;
                uint2 k0 = khl[r0 + nn], k1 = khl[r1 + nn];
                unsigned bh2[2] = { k0.x, k1.x };
                unsigned bl2[2] = { k0.y, k1.y };
                mma_bf16(sacc[j], qh[kc], bh2);
                mma_bf16(sacc[j], qh[kc], bl2);
                mma_bf16(sacc[j], ql[kc], bh2);
            }
        }

        // ---- + rpe bias (pair table: 4 LDS per 2 bias values) ----
#pragma unroll
        for (int j = 0; j < 8; j++) {
#pragma unroll
            for (int e = 0; e < 2; e++) {
                int nn = (j << 3) + (tig << 1) + e;
                float4 w = w4[nn];
                int idxb = ib[nn];
                int ia = idxb + moff0;
                unsigned u0 = tbp[ia], u1 = tbp[ia + 69];
                sacc[j][e] += w.x * __uint_as_float(u0 << 16)
                            + w.y * __uint_as_float(u0 & 0xffff0000u)
                            + w.z * __uint_as_float(u1 << 16)
                            + w.w * __uint_as_float(u1 & 0xffff0000u);
                int ic = idxb + moff1;
                u0 = tbp[ic]; u1 = tbp[ic + 69];
                sacc[j][2 + e] += w.x * __uint_as_float(u0 << 16)
                                + w.y * __uint_as_float(u0 & 0xffff0000u)
                                + w.z * __uint_as_float(u1 << 16)
                                + w.w * __uint_as_float(u1 & 0xffff0000u);
            }
        }

        // ---- online softmax; P packed into registers ----
        float tm0 = -1e30f, tm1 = -1e30f;
#pragma unroll
        for (int j = 0; j < 8; j++) {
            tm0 = fmaxf(tm0, fmaxf(sacc[j][0], sacc[j][1]));
            tm1 = fmaxf(tm1, fmaxf(sacc[j][2], sacc[j][3]));
        }
        tm0 = fmaxf(tm0, __shfl_xor_sync(0xffffffffu, tm0, 1));
        tm0 = fmaxf(tm0, __shfl_xor_sync(0xffffffffu, tm0, 2));
        tm1 = fmaxf(tm1, __shfl_xor_sync(0xffffffffu, tm1, 1));
        tm1 = fmaxf(tm1, __shfl_xor_sync(0xffffffffu, tm1, 2));
        float nm0 = fmaxf(runm0, tm0), nm1 = fmaxf(runm1, tm1);
        float corr0 = __expf(runm0 - nm0), corr1 = __expf(runm1 - nm1);
        runm0 = nm0; runm1 = nm1;
        float lsum0 = 0.f, lsum1 = 0.f;
        unsigned pAh[8], pAl[8], pBh[8], pBl[8];
#pragma unroll
        for (int j = 0; j < 8; j++) {
            float p0 = __expf(sacc[j][0] - nm0);
            float p1 = __expf(sacc[j][1] - nm0);
            float p2 = __expf(sacc[j][2] - nm1);
            float p3 = __expf(sacc[j][3] - nm1);
            lsum0 += p0 + p1; lsum1 += p2 + p3;
            bsplit2(p0, p1, pAh[j], pAl[j]);
            bsplit2(p2, p3, pBh[j], pBl[j]);
        }
        rsum0 = rsum0 * corr0 + lsum0;
        rsum1 = rsum1 * corr1 + lsum1;
#pragma unroll
        for (int ct = 0; ct < 4; ct++) {
            oacc[ct][0] *= corr0; oacc[ct][1] *= corr0;
            oacc[ct][2] *= corr1; oacc[ct][3] *= corr1;
        }

        // ---- O += P V (B-fragments via LDS.64) ----
#pragma unroll
        for (int ch = 0; ch < 4; ch++) {
            unsigned ah[4] = { pAh[2 * ch], pBh[2 * ch], pAh[2 * ch + 1], pBh[2 * ch + 1] };
            unsigned al[4] = { pAl[2 * ch], pBl[2 * ch], pAl[2 * ch + 1], pBl[2 * ch + 1] };
            int npA = (ch << 3) + tig;
#pragma unroll
            for (int ct = 0; ct < 4; ct++) {
                int cc = (ct << 3) + gid;
                uint2 v0 = vhl[npA * 36 + cc];
                uint2 v1 = vhl[(npA + 4) * 36 + cc];
                unsigned bh2[2] = { v0.x, v1.x };
                unsigned bl2[2] = { v0.y, v1.y };
                mma_bf16(oacc[ct], ah, bh2);
                mma_bf16(oacc[ct], ah, bl2);
                mma_bf16(oacc[ct], al, bh2);
            }
        }
    }

    rsum0 += __shfl_xor_sync(0xffffffffu, rsum0, 1);
    rsum0 += __shfl_xor_sync(0xffffffffu, rsum0, 2);
    rsum1 += __shfl_xor_sync(0xffffffffu, rsum1, 1);
    rsum1 += __shfl_xor_sync(0xffffffffu, rsum1, 2);
    float inv0 = 1.f / rsum0, inv1 = 1.f / rsum1;

    // normalize + transpose via smem (reuse K/V region as float [64][68])
    float* obuf = (float*)sm_;
    __syncthreads();
#pragma unroll
    for (int ct = 0; ct < 4; ct++) {
        int cc = (ct << 3) + (tig << 1);
        *(float2*)&obuf[(wm + gid) * 68 + cc] =
            make_float2(oacc[ct][0] * inv0, oacc[ct][1] * inv0);
        *(float2*)&obuf[(wm + gid + 8) * 68 + cc] =
            make_float2(oacc[ct][2] * inv1, oacc[ct][3] * inv1);
    }
    __syncthreads();
    float* ob = g_o + (size_t)(b * C_ + hd * HC_) * N_;
    for (int i = tid; i < 2048; i += 128) {
        int c = i >> 6, m = i & 63;
        ob[(size_t)c * N_ + m0 + m] = obuf[m * 68 + c];
    }
}

// ============================================================
extern "C" void kernel_launch(void* const* d_in, const int* in_sizes, int n_in,
                              void* d_out, int out_size) {
    const float* q_feat = (const float*)d_in[0];
    const float* kv_feat = (const float*)d_in[1];
    const float* Wq = (const float*)d_in[2];
    const float* bq = (const float*)d_in[3];
    const float* Wk = (const float*)d_in[4];
    const float* bk = (const float*)d_in[5];
    const float* Wv = (const float*)d_in[6];
    const float* bv = (const float*)d_in[7];
    const float* Wo = (const float*)d_in[8];
    const float* bo = (const float*)d_in[9];
    const float* dw_w = (const float*)d_in[10];
    const float* dw_b = (const float*)d_in[11];
    const float* ln_w = (const float*)d_in[12];
    const float* ln_b = (const float*)d_in[13];
    const float* pw_w = (const float*)d_in[14];
    const float* rpe  = (const float*)d_in[15];
    float* out = (float*)d_out;

    float *gq, *gxs, *gk, *gv, *go;
    cudaGetSymbolAddress((void**)&gq,  g_q);
    cudaGetSymbolAddress((void**)&gxs, g_xs);
    cudaGetSymbolAddress((void**)&gk,  g_k);
    cudaGetSymbolAddress((void**)&gv,  g_v);
    cudaGetSymbolAddress((void**)&go,  g_o);

    static int smem_set = 0;
    if (!smem_set) {
        cudaFuncSetAttribute(flash_kernel,
                             cudaFuncAttributeMaxDynamicSharedMemorySize, FL_SMEM);
        smem_set = 1;
    }

    dim3 gemm_grid(N_ / 64, C_ / 64, B_);
    dim3 kv_grid(N_ / 64, C_ / 64, B_ * 2);

    gemm_proj<<<gemm_grid, 128>>>(Wq, bq, q_feat, gq);
    offset_sample_kernel<<<(BG_ * N_ * 4) / 256, 256>>>(dw_w, dw_b, ln_w, ln_b, pw_w, kv_feat);
    gemm_kv<<<kv_grid, 128>>>(Wk, bk, Wv, bv, gxs, gk, gv);
    flash_kernel<<<dim3(N_ / 64, B_ * NH_), 128, FL_SMEM>>>(rpe);
    gemm_proj<<<gemm_grid, 128>>>(Wo, bo, go, out);
}